// round 5
// baseline (speedup 1.0000x reference)
#include <cuda_runtime.h>
#include <cuda_bf16.h>
#include <cstdint>

// Problem constants
#define NB 32
#define NS 512
#define NH 16
#define NDH 64
#define NDM 1024
#define NT 512
#define BH (NB*NH)          // 512

// ---------------- global scratch (static; allocation APIs forbidden) -------
__device__ float g_K [BH*NS*NDH];
__device__ float g_V [BH*NS*NDH];
// bf16 split operands
__device__ __nv_bfloat16 g_Qh [(size_t)BH*NS*NDH];  // Q [bh][s][d]
__device__ __nv_bfloat16 g_Ql [(size_t)BH*NS*NDH];
__device__ __nv_bfloat16 g_Kth[(size_t)BH*NDH*NS];  // K^T [bh][d][s]
__device__ __nv_bfloat16 g_Ktl[(size_t)BH*NDH*NS];
__device__ __nv_bfloat16 g_Vth[(size_t)BH*NDH*NS];  // V^T [bh][d][s]
__device__ __nv_bfloat16 g_Vtl[(size_t)BH*NDH*NS];
__device__ __nv_bfloat16 g_KEh[(size_t)BH*NT*NDH];  // KE (incl E_b) [bh][t][d]
__device__ __nv_bfloat16 g_KEl[(size_t)BH*NT*NDH];
__device__ __nv_bfloat16 g_VFth[(size_t)BH*NDH*NT]; // VF^T (incl F_b) [bh][d][t]
__device__ __nv_bfloat16 g_VFtl[(size_t)BH*NDH*NT];
__device__ __nv_bfloat16 g_Ewh[NT*NS], g_Ewl[NT*NS];
__device__ __nv_bfloat16 g_Fwh[NT*NS], g_Fwl[NT*NS];
__device__ __nv_bfloat16 g_Owh[NDM*NDM], g_Owl[NDM*NDM];
__device__ __nv_bfloat16 g_HOh[(size_t)BH*NS*NDH];  // head_out [bh][s][d]
__device__ __nv_bfloat16 g_HOl[(size_t)BH*NS*NDH];
// Fallbacks in case out buffer holds only one of the two outputs
__device__ float g_ATTN_FB[(size_t)BH*NS*NT];
__device__ float g_MHA_FB [(size_t)NB*NS*NDM];

// ---------------- helpers ---------------------------------------------------
__device__ __forceinline__ void mma16816(float c[4],
                                         uint32_t a0, uint32_t a1, uint32_t a2, uint32_t a3,
                                         uint32_t b0, uint32_t b1)
{
    asm volatile(
        "mma.sync.aligned.m16n8k16.row.col.f32.bf16.bf16.f32 "
        "{%0,%1,%2,%3}, {%4,%5,%6,%7}, {%8,%9}, {%0,%1,%2,%3};"
        : "+f"(c[0]), "+f"(c[1]), "+f"(c[2]), "+f"(c[3])
        : "r"(a0), "r"(a1), "r"(a2), "r"(a3), "r"(b0), "r"(b1));
}
// split two floats -> packed bf16x2 hi + lo words
__device__ __forceinline__ void split2(float x, float y, uint32_t& hi, uint32_t& lo)
{
    __nv_bfloat162 h = __floats2bfloat162_rn(x, y);
    float hx = __bfloat162float(h.x), hy = __bfloat162float(h.y);
    __nv_bfloat162 l = __floats2bfloat162_rn(x - hx, y - hy);
    hi = *(uint32_t*)&h;
    lo = *(uint32_t*)&l;
}

// ---------------------------------------------------------------------------
// Kernel 1: per-head Q/K/V projection (fp32). Q written as bf16 split.
// ---------------------------------------------------------------------------
__global__ void k_qkv(const float* __restrict__ qin, const float* __restrict__ kin,
                      const float* __restrict__ vin,
                      const float* __restrict__ Wq, const float* __restrict__ bq,
                      const float* __restrict__ Wk, const float* __restrict__ bk,
                      const float* __restrict__ Wv, const float* __restrict__ bv)
{
    __shared__ float WT[64][65];
    __shared__ float Xs[64][64];
    int bh = blockIdx.x;
    int b  = bh >> 4, h = bh & 15;
    int s0 = blockIdx.y << 6;
    const float *in, *W, *bias; float* out = nullptr;
    if (blockIdx.z == 0)      { in = qin; W = Wq; bias = bq; }
    else if (blockIdx.z == 1) { in = kin; W = Wk; bias = bk; out = g_K; }
    else                      { in = vin; W = Wv; bias = bv; out = g_V; }
    int tid = threadIdx.x;
    for (int i = tid; i < 4096; i += 256) {
        int r = i >> 6, c = i & 63;
        WT[c][r] = W[(h*64 + r)*64 + c];
        Xs[r][c] = in[((b*NS) + s0 + r)*64 + c];
    }
    __syncthreads();
    int e  = tid & 63;
    int ty = tid >> 6;
    float bval = bias[h*64 + e];
    float acc[16];
#pragma unroll
    for (int j = 0; j < 16; j++) acc[j] = bval;
#pragma unroll 4
    for (int d = 0; d < 64; d++) {
        float w = WT[d][e];
#pragma unroll
        for (int j = 0; j < 16; j++) acc[j] += Xs[ty + j*4][d] * w;
    }
    if (blockIdx.z == 0) {
#pragma unroll
        for (int j = 0; j < 16; j++) {
            size_t idx = ((size_t)bh*NS + s0 + ty + j*4)*64 + e;
            __nv_bfloat16 hb = __float2bfloat16(acc[j]);
            g_Qh[idx] = hb;
            g_Ql[idx] = __float2bfloat16(acc[j] - __bfloat162float(hb));
        }
    } else {
#pragma unroll
        for (int j = 0; j < 16; j++)
            out[((size_t)bh*NS + s0 + ty + j*4)*64 + e] = acc[j];
    }
}

// ---------------------------------------------------------------------------
// Kernel: elementwise bf16 split (hi + lo)
// ---------------------------------------------------------------------------
__global__ void k_split(const float* __restrict__ s, __nv_bfloat16* __restrict__ h,
                        __nv_bfloat16* __restrict__ l, int n)
{
    int i = blockIdx.x * 256 + threadIdx.x;
    if (i < n) {
        float v = s[i];
        __nv_bfloat16 hb = __float2bfloat16(v);
        h[i] = hb;
        l[i] = __float2bfloat16(v - __bfloat162float(hb));
    }
}

// ---------------------------------------------------------------------------
// Kernel: transpose K/V to [d][s] + bf16 split
// ---------------------------------------------------------------------------
__global__ void k_prep_kv()
{
    __shared__ float ts[64][65];
    int bh = blockIdx.x, s0 = blockIdx.y << 6;
    const float* src = (blockIdx.z == 0 ? g_K : g_V) + (size_t)bh*NS*NDH;
    __nv_bfloat16* dh = (blockIdx.z == 0 ? g_Kth : g_Vth) + (size_t)bh*NDH*NS;
    __nv_bfloat16* dl = (blockIdx.z == 0 ? g_Ktl : g_Vtl) + (size_t)bh*NDH*NS;
    int tid = threadIdx.x;
    for (int i = tid; i < 4096; i += 256) {
        int r = i >> 6, c = i & 63;
        ts[r][c] = src[(s0 + r)*64 + c];
    }
    __syncthreads();
    for (int i = tid; i < 4096; i += 256) {
        int d = i >> 6, r = i & 63;
        float v = ts[r][d];
        __nv_bfloat16 hb = __float2bfloat16(v);
        dh[(size_t)d*NS + s0 + r] = hb;
        dl[(size_t)d*NS + s0 + r] = __float2bfloat16(v - __bfloat162float(hb));
    }
}

// ===========================================================================
// mma.sync GEMM chunk body (validated round 4).
// Block 256 = 8 warps, warp (wm = wid&3, wn = wid>>2) owns 32(m)x32(n).
// smem: Ah[128][33] Al[128][33] Bh[64][33] Bl[64][33] (u32 bf16-pairs).
// ===========================================================================
#define MMA_CHUNK_COMPUTE()                                                      \
    _Pragma("unroll")                                                            \
    for (int ks = 0; ks < 4; ks++) {                                             \
        int kw = ks*8;                                                           \
        uint32_t ah[2][4], al[2][4];                                             \
        _Pragma("unroll")                                                        \
        for (int mi = 0; mi < 2; mi++) {                                         \
            int base = (m0w + mi*16 + g)*33 + kw + t4;                           \
            ah[mi][0] = Ah32[base];     ah[mi][1] = Ah32[base + 264];            \
            ah[mi][2] = Ah32[base + 4]; ah[mi][3] = Ah32[base + 268];            \
            al[mi][0] = Al32[base];     al[mi][1] = Al32[base + 264];            \
            al[mi][2] = Al32[base + 4]; al[mi][3] = Al32[base + 268];            \
        }                                                                        \
        _Pragma("unroll")                                                        \
        for (int nj = 0; nj < 4; nj++) {                                         \
            int bb = (n0w + nj*8 + g)*33 + kw + t4;                              \
            uint32_t b0h = Bh32[bb], b1h = Bh32[bb + 4];                         \
            uint32_t b0l = Bl32[bb], b1l = Bl32[bb + 4];                         \
            _Pragma("unroll")                                                    \
            for (int mi = 0; mi < 2; mi++) {                                     \
                mma16816(acc[mi][nj], ah[mi][0],ah[mi][1],ah[mi][2],ah[mi][3], b0h,b1h); \
                mma16816(acc[mi][nj], ah[mi][0],ah[mi][1],ah[mi][2],ah[mi][3], b0l,b1l); \
                mma16816(acc[mi][nj], al[mi][0],al[mi][1],al[mi][2],al[mi][3], b0h,b1h); \
            }                                                                    \
        }                                                                        \
    }

// ---------------------------------------------------------------------------
// k_ke_mma: D[t(128)][d(64)] = sum_s Ew[t][s]*Kt[d][s] + Eb[t]
// epilogue: write bf16-split KE [bh][t][d] directly (natural layout).
// grid (BH, 4), block 256, dyn smem 50688
// ---------------------------------------------------------------------------
__global__ void __launch_bounds__(256, 2) k_ke_mma(const float* __restrict__ Eb)
{
    extern __shared__ uint32_t sm32[];
    uint32_t* Ah32 = sm32;
    uint32_t* Al32 = Ah32 + 128*33;
    uint32_t* Bh32 = Al32 + 128*33;
    uint32_t* Bl32 = Bh32 + 64*33;
    int tid = threadIdx.x, wid = tid >> 5, lane = tid & 31;
    int g = lane >> 2, t4 = lane & 3;
    int m0w = (wid & 3)*32, n0w = (wid >> 2)*32;
    int bh = blockIdx.x, t0 = blockIdx.y << 7;

    float acc[2][4][4];
#pragma unroll
    for (int mi = 0; mi < 2; mi++)
#pragma unroll
        for (int nj = 0; nj < 4; nj++)
#pragma unroll
            for (int q = 0; q < 4; q++) acc[mi][nj][q] = 0.f;

    const uint32_t* gAh = (const uint32_t*)g_Ewh + (size_t)t0*256;
    const uint32_t* gAl = (const uint32_t*)g_Ewl + (size_t)t0*256;
    const uint32_t* gBh = (const uint32_t*)g_Kth + (size_t)bh*16384;
    const uint32_t* gBl = (const uint32_t*)g_Ktl + (size_t)bh*16384;

    for (int ch = 0; ch < 8; ch++) {
        int sw = ch*32;
        __syncthreads();
        for (int i = tid; i < 4096; i += 256) {
            int r = i >> 5, c = i & 31;
            Ah32[r*33 + c] = gAh[(size_t)r*256 + sw + c];
            Al32[r*33 + c] = gAl[(size_t)r*256 + sw + c];
        }
        for (int i = tid; i < 2048; i += 256) {
            int r = i >> 5, c = i & 31;
            Bh32[r*33 + c] = gBh[(size_t)r*256 + sw + c];
            Bl32[r*33 + c] = gBl[(size_t)r*256 + sw + c];
        }
        __syncthreads();
        MMA_CHUNK_COMPUTE();
    }

    // epilogue: +Eb, split -> g_KEh/g_KEl [bh][t][d]
    size_t base = (size_t)bh*NT*NDH;
#pragma unroll
    for (int mi = 0; mi < 2; mi++) {
        int m = m0w + mi*16 + g;
        float e0 = Eb[t0 + m];
        float e1 = Eb[t0 + m + 8];
#pragma unroll
        for (int nj = 0; nj < 4; nj++) {
            int n = n0w + nj*8 + t4*2;
            uint32_t hi, lo;
            size_t i0 = base + (size_t)(t0 + m)*NDH + n;
            split2(acc[mi][nj][0] + e0, acc[mi][nj][1] + e0, hi, lo);
            *(uint32_t*)(g_KEh + i0) = hi;  *(uint32_t*)(g_KEl + i0) = lo;
            size_t i1 = base + (size_t)(t0 + m + 8)*NDH + n;
            split2(acc[mi][nj][2] + e1, acc[mi][nj][3] + e1, hi, lo);
            *(uint32_t*)(g_KEh + i1) = hi;  *(uint32_t*)(g_KEl + i1) = lo;
        }
    }
}

// ---------------------------------------------------------------------------
// k_vf_mma: D[t(128)][d(64)] = sum_s Fw[t][s]*Vt[d][s] + Fb[t]
// epilogue: write bf16-split VF^T [bh][d][t] (transposed via smem stage).
// ---------------------------------------------------------------------------
__global__ void __launch_bounds__(256, 2) k_vf_mma(const float* __restrict__ Fb)
{
    extern __shared__ uint32_t sm32[];
    uint32_t* Ah32 = sm32;
    uint32_t* Al32 = Ah32 + 128*33;
    uint32_t* Bh32 = Al32 + 128*33;
    uint32_t* Bl32 = Bh32 + 64*33;
    int tid = threadIdx.x, wid = tid >> 5, lane = tid & 31;
    int g = lane >> 2, t4 = lane & 3;
    int m0w = (wid & 3)*32, n0w = (wid >> 2)*32;
    int bh = blockIdx.x, t0 = blockIdx.y << 7;

    float acc[2][4][4];
#pragma unroll
    for (int mi = 0; mi < 2; mi++)
#pragma unroll
        for (int nj = 0; nj < 4; nj++)
#pragma unroll
            for (int q = 0; q < 4; q++) acc[mi][nj][q] = 0.f;

    const uint32_t* gAh = (const uint32_t*)g_Fwh + (size_t)t0*256;
    const uint32_t* gAl = (const uint32_t*)g_Fwl + (size_t)t0*256;
    const uint32_t* gBh = (const uint32_t*)g_Vth + (size_t)bh*16384;
    const uint32_t* gBl = (const uint32_t*)g_Vtl + (size_t)bh*16384;

    for (int ch = 0; ch < 8; ch++) {
        int sw = ch*32;
        __syncthreads();
        for (int i = tid; i < 4096; i += 256) {
            int r = i >> 5, c = i & 31;
            Ah32[r*33 + c] = gAh[(size_t)r*256 + sw + c];
            Al32[r*33 + c] = gAl[(size_t)r*256 + sw + c];
        }
        for (int i = tid; i < 2048; i += 256) {
            int r = i >> 5, c = i & 31;
            Bh32[r*33 + c] = gBh[(size_t)r*256 + sw + c];
            Bl32[r*33 + c] = gBl[(size_t)r*256 + sw + c];
        }
        __syncthreads();
        MMA_CHUNK_COMPUTE();
    }

    // epilogue: stage transposed [d][t] fp32 (+Fb), then split-store rows
    __syncthreads();
    float* Sg = (float*)sm32;          // [64][129]
#pragma unroll
    for (int mi = 0; mi < 2; mi++) {
        int m = m0w + mi*16 + g;
        float f0 = Fb[t0 + m];
        float f1 = Fb[t0 + m + 8];
#pragma unroll
        for (int nj = 0; nj < 4; nj++) {
            int n = n0w + nj*8 + t4*2;
            Sg[n*129 + m]         = acc[mi][nj][0] + f0;
            Sg[(n+1)*129 + m]     = acc[mi][nj][1] + f0;
            Sg[n*129 + m + 8]     = acc[mi][nj][2] + f1;
            Sg[(n+1)*129 + m + 8] = acc[mi][nj][3] + f1;
        }
    }
    __syncthreads();
    size_t base = (size_t)bh*NDH*NT;
    for (int i = tid; i < 4096; i += 256) {
        int d = i >> 6, mm = (i & 63)*2;
        uint32_t hi, lo;
        split2(Sg[d*129 + mm], Sg[d*129 + mm + 1], hi, lo);
        size_t idx = base + (size_t)d*NT + t0 + mm;
        *(uint32_t*)(g_VFth + idx) = hi;
        *(uint32_t*)(g_VFtl + idx) = lo;
    }
}

// ---------------------------------------------------------------------------
// k_attn_mma: scores = 0.125 * Q·KE^T (KE as [t][d] B-operand), softmax, write attn.
// grid (BH, 16 s-tiles of 32), block 256 (8 warps; warp w owns t-slice w*64..+64)
// smem: KEh[512][33] KEl[512][33] Qh[32][33] Ql[32][33] (u32) + red bufs
// ---------------------------------------------------------------------------
__global__ void __launch_bounds__(256, 1) k_attn_mma(float* __restrict__ attn_out)
{
    extern __shared__ uint32_t sm32[];
    uint32_t* KEh32 = sm32;
    uint32_t* KEl32 = sm32 + 16896;
    uint32_t* Qh32  = sm32 + 33792;
    uint32_t* Ql32  = sm32 + 34848;
    float* sredm = (float*)(sm32 + 35904);   // [8][32]
    float* sreds = (float*)(sm32 + 36160);   // [8][32]
    int tid = threadIdx.x, wid = tid >> 5, lane = tid & 31;
    int g = lane >> 2, t4 = lane & 3;
    int bh = blockIdx.x, s0 = blockIdx.y << 5;

    const uint32_t* gKEh = (const uint32_t*)g_KEh + (size_t)bh*16384;
    const uint32_t* gKEl = (const uint32_t*)g_KEl + (size_t)bh*16384;
    for (int i = tid; i < 16384; i += 256) {
        int r = i >> 5, c = i & 31;
        KEh32[r*33 + c] = gKEh[i];
        KEl32[r*33 + c] = gKEl[i];
    }
    const uint32_t* gQh = (const uint32_t*)g_Qh + ((size_t)bh*NS + s0)*32;
    const uint32_t* gQl = (const uint32_t*)g_Ql + ((size_t)bh*NS + s0)*32;
    for (int i = tid; i < 1024; i += 256) {
        int r = i >> 5, c = i & 31;
        Qh32[r*33 + c] = gQh[i];
        Ql32[r*33 + c] = gQl[i];
    }
    __syncthreads();

    float acc[2][8][4];
#pragma unroll
    for (int mi = 0; mi < 2; mi++)
#pragma unroll
        for (int nj = 0; nj < 8; nj++)
#pragma unroll
            for (int q = 0; q < 4; q++) acc[mi][nj][q] = 0.f;

#pragma unroll
    for (int ks = 0; ks < 4; ks++) {
        int kw = ks*8;
        uint32_t ah[2][4], al[2][4];
#pragma unroll
        for (int mi = 0; mi < 2; mi++) {
            int base = (mi*16 + g)*33 + kw + t4;
            ah[mi][0] = Qh32[base];     ah[mi][1] = Qh32[base + 264];
            ah[mi][2] = Qh32[base + 4]; ah[mi][3] = Qh32[base + 268];
            al[mi][0] = Ql32[base];     al[mi][1] = Ql32[base + 264];
            al[mi][2] = Ql32[base + 4]; al[mi][3] = Ql32[base + 268];
        }
#pragma unroll
        for (int nj = 0; nj < 8; nj++) {
            int bb = (wid*64 + nj*8 + g)*33 + kw + t4;
            uint32_t b0h = KEh32[bb], b1h = KEh32[bb + 4];
            uint32_t b0l = KEl32[bb], b1l = KEl32[bb + 4];
#pragma unroll
            for (int mi = 0; mi < 2; mi++) {
                mma16816(acc[mi][nj], ah[mi][0],ah[mi][1],ah[mi][2],ah[mi][3], b0h,b1h);
                mma16816(acc[mi][nj], ah[mi][0],ah[mi][1],ah[mi][2],ah[mi][3], b0l,b1l);
                mma16816(acc[mi][nj], al[mi][0],al[mi][1],al[mi][2],al[mi][3], b0h,b1h);
            }
        }
    }

    // scale + warp-local row max over this warp's 64 cols
    float lm[2][2];
#pragma unroll
    for (int mi = 0; mi < 2; mi++) { lm[mi][0] = -1e30f; lm[mi][1] = -1e30f; }
#pragma unroll
    for (int mi = 0; mi < 2; mi++)
#pragma unroll
        for (int nj = 0; nj < 8; nj++) {
#pragma unroll
            for (int q = 0; q < 4; q++) acc[mi][nj][q] *= 0.125f;
            lm[mi][0] = fmaxf(lm[mi][0], fmaxf(acc[mi][nj][0], acc[mi][nj][1]));
            lm[mi][1] = fmaxf(lm[mi][1], fmaxf(acc[mi][nj][2], acc[mi][nj][3]));
        }
#pragma unroll
    for (int mi = 0; mi < 2; mi++)
#pragma unroll
        for (int hh = 0; hh < 2; hh++) {
            lm[mi][hh] = fmaxf(lm[mi][hh], __shfl_xor_sync(0xffffffffu, lm[mi][hh], 1));
            lm[mi][hh] = fmaxf(lm[mi][hh], __shfl_xor_sync(0xffffffffu, lm[mi][hh], 2));
        }
    if (t4 == 0) {
#pragma unroll
        for (int mi = 0; mi < 2; mi++) {
            sredm[wid*32 + mi*16 + g]     = lm[mi][0];
            sredm[wid*32 + mi*16 + g + 8] = lm[mi][1];
        }
    }
    __syncthreads();
    float rowm[2][2];
#pragma unroll
    for (int mi = 0; mi < 2; mi++)
#pragma unroll
        for (int hh = 0; hh < 2; hh++) {
            int row = mi*16 + g + hh*8;
            float m = sredm[row];
#pragma unroll
            for (int w = 1; w < 8; w++) m = fmaxf(m, sredm[w*32 + row]);
            rowm[mi][hh] = m;
        }

    // exp + warp-local row sum
    float ls[2][2] = {{0.f,0.f},{0.f,0.f}};
#pragma unroll
    for (int mi = 0; mi < 2; mi++)
#pragma unroll
        for (int nj = 0; nj < 8; nj++) {
            acc[mi][nj][0] = __expf(acc[mi][nj][0] - rowm[mi][0]);
            acc[mi][nj][1] = __expf(acc[mi][nj][1] - rowm[mi][0]);
            acc[mi][nj][2] = __expf(acc[mi][nj][2] - rowm[mi][1]);
            acc[mi][nj][3] = __expf(acc[mi][nj][3] - rowm[mi][1]);
            ls[mi][0] += acc[mi][nj][0] + acc[mi][nj][1];
            ls[mi][1] += acc[mi][nj][2] + acc[mi][nj][3];
        }
#pragma unroll
    for (int mi = 0; mi < 2; mi++)
#pragma unroll
        for (int hh = 0; hh < 2; hh++) {
            ls[mi][hh] += __shfl_xor_sync(0xffffffffu, ls[mi][hh], 1);
            ls[mi][hh] += __shfl_xor_sync(0xffffffffu, ls[mi][hh], 2);
        }
    if (t4 == 0) {
#pragma unroll
        for (int mi = 0; mi < 2; mi++) {
            sreds[wid*32 + mi*16 + g]     = ls[mi][0];
            sreds[wid*32 + mi*16 + g + 8] = ls[mi][1];
        }
    }
    __syncthreads();
    float inv[2][2];
#pragma unroll
    for (int mi = 0; mi < 2; mi++)
#pragma unroll
        for (int hh = 0; hh < 2; hh++) {
            int row = mi*16 + g + hh*8;
            float s = 0.f;
#pragma unroll
            for (int w = 0; w < 8; w++) s += sreds[w*32 + row];
            inv[mi][hh] = 1.f / s;
        }

    // write attn
#pragma unroll
    for (int mi = 0; mi < 2; mi++) {
        size_t r0 = ((size_t)bh*NS + s0 + mi*16 + g)*NT;
        size_t r1 = r0 + 8*NT;
#pragma unroll
        for (int nj = 0; nj < 8; nj++) {
            int col = wid*64 + nj*8 + 2*t4;
            float2 v0 = make_float2(acc[mi][nj][0]*inv[mi][0], acc[mi][nj][1]*inv[mi][0]);
            float2 v1 = make_float2(acc[mi][nj][2]*inv[mi][1], acc[mi][nj][3]*inv[mi][1]);
            *(float2*)(attn_out + r0 + col) = v0;
            *(float2*)(attn_out + r1 + col) = v1;
        }
    }
}

// ---------------------------------------------------------------------------
// k_ho_mma: HO[s(128)][d(64)] = sum_t attn[s][t]*VFt[d][t]
// A = attn fp32 split on-the-fly; B = VF^T split; epilogue HO bf16 split.
// grid (BH, 4), block 256, dyn smem 50688
// ---------------------------------------------------------------------------
__global__ void __launch_bounds__(256, 2) k_ho_mma(const float* __restrict__ attn)
{
    extern __shared__ uint32_t sm32[];
    uint32_t* Ah32 = sm32;
    uint32_t* Al32 = Ah32 + 128*33;
    uint32_t* Bh32 = Al32 + 128*33;
    uint32_t* Bl32 = Bh32 + 64*33;
    int tid = threadIdx.x, wid = tid >> 5, lane = tid & 31;
    int g = lane >> 2, t4 = lane & 3;
    int m0w = (wid & 3)*32, n0w = (wid >> 2)*32;
    int bh = blockIdx.x, s0 = blockIdx.y << 7;

    float acc[2][4][4];
#pragma unroll
    for (int mi = 0; mi < 2; mi++)
#pragma unroll
        for (int nj = 0; nj < 4; nj++)
#pragma unroll
            for (int q = 0; q < 4; q++) acc[mi][nj][q] = 0.f;

    const float* gA = attn + ((size_t)bh*NS + s0)*NT;
    const uint32_t* gBh = (const uint32_t*)g_VFth + (size_t)bh*16384;
    const uint32_t* gBl = (const uint32_t*)g_VFtl + (size_t)bh*16384;

    for (int ch = 0; ch < 8; ch++) {
        __syncthreads();
        for (int i = tid; i < 4096; i += 256) {
            int r = i >> 5, c = i & 31;
            float2 f = *(const float2*)(gA + (size_t)r*NT + ch*64 + 2*c);
            uint32_t hi, lo;
            split2(f.x, f.y, hi, lo);
            Ah32[r*33 + c] = hi;
            Al32[r*33 + c] = lo;
        }
        for (int i = tid; i < 2048; i += 256) {
            int r = i >> 5, c = i & 31;
            Bh32[r*33 + c] = gBh[(size_t)r*256 + ch*32 + c];
            Bl32[r*33 + c] = gBl[(size_t)r*256 + ch*32 + c];
        }
        __syncthreads();
        MMA_CHUNK_COMPUTE();
    }

    // epilogue: split HO -> g_HOh/g_HOl [bh][s][d]
    size_t base = (size_t)bh*NS*NDH;
#pragma unroll
    for (int mi = 0; mi < 2; mi++) {
        int m = m0w + mi*16 + g;
#pragma unroll
        for (int nj = 0; nj < 4; nj++) {
            int n = n0w + nj*8 + t4*2;
            uint32_t hi, lo;
            size_t i0 = base + (size_t)(s0 + m)*NDH + n;
            split2(acc[mi][nj][0], acc[mi][nj][1], hi, lo);
            *(uint32_t*)(g_HOh + i0) = hi;  *(uint32_t*)(g_HOl + i0) = lo;
            size_t i1 = base + (size_t)(s0 + m + 8)*NDH + n;
            split2(acc[mi][nj][2], acc[mi][nj][3], hi, lo);
            *(uint32_t*)(g_HOh + i1) = hi;  *(uint32_t*)(g_HOl + i1) = lo;
        }
    }
}

// ---------------------------------------------------------------------------
// k_out_mma: out[m(128)][n(64)] = sum_k HO[m][k]*Ow[n][k] + Ob[n]
// ---------------------------------------------------------------------------
__global__ void __launch_bounds__(256, 2) k_out_mma(const float* __restrict__ Ob,
                                                    float* __restrict__ out)
{
    extern __shared__ uint32_t sm32[];
    uint32_t* Ah32 = sm32;
    uint32_t* Al32 = Ah32 + 128*33;
    uint32_t* Bh32 = Al32 + 128*33;
    uint32_t* Bl32 = Bh32 + 64*33;
    int tid = threadIdx.x, wid = tid >> 5, lane = tid & 31;
    int g = lane >> 2, t4 = lane & 3;
    int m0w = (wid & 3)*32, n0w = (wid >> 2)*32;
    int m0 = blockIdx.x << 7;
    int b  = blockIdx.x >> 2;
    int sbase = (blockIdx.x & 3) << 7;
    int n0 = blockIdx.y << 6;

    float acc[2][4][4];
#pragma unroll
    for (int mi = 0; mi < 2; mi++)
#pragma unroll
        for (int nj = 0; nj < 4; nj++)
#pragma unroll
            for (int q = 0; q < 4; q++) acc[mi][nj][q] = 0.f;

    for (int kc = 0; kc < 16; kc++) {
        const uint32_t* gAh = (const uint32_t*)g_HOh + ((size_t)(b*NH + kc)*NS + sbase)*32;
        const uint32_t* gAl = (const uint32_t*)g_HOl + ((size_t)(b*NH + kc)*NS + sbase)*32;
        const uint32_t* gBh = (const uint32_t*)g_Owh + (size_t)n0*512 + kc*32;
        const uint32_t* gBl = (const uint32_t*)g_Owl + (size_t)n0*512 + kc*32;
        __syncthreads();
        for (int i = tid; i < 4096; i += 256) {
            int r = i >> 5, c = i & 31;
            Ah32[r*33 + c] = gAh[(size_t)r*32 + c];
            Al32[r*33 + c] = gAl[(size_t)r*32 + c];
        }
        for (int i = tid; i < 2048; i += 256) {
            int r = i >> 5, c = i & 31;
            Bh32[r*33 + c] = gBh[(size_t)r*512 + c];
            Bl32[r*33 + c] = gBl[(size_t)r*512 + c];
        }
        __syncthreads();
        MMA_CHUNK_COMPUTE();
    }

    __syncthreads();
    float* Sg = (float*)sm32;          // [128][65]
#pragma unroll
    for (int mi = 0; mi < 2; mi++) {
        int m = m0w + mi*16 + g;
#pragma unroll
        for (int nj = 0; nj < 4; nj++) {
            int n = n0w + nj*8 + t4*2;
            float o0 = Ob[n0 + n];
            float o1 = Ob[n0 + n + 1];
            Sg[m*65 + n]         = acc[mi][nj][0] + o0;
            Sg[m*65 + n + 1]     = acc[mi][nj][1] + o1;
            Sg[(m+8)*65 + n]     = acc[mi][nj][2] + o0;
            Sg[(m+8)*65 + n + 1] = acc[mi][nj][3] + o1;
        }
    }
    __syncthreads();
    for (int i = tid; i < 8192; i += 256) {
        int r = i >> 6, c = i & 63;
        out[(size_t)(m0 + r)*NDM + n0 + c] = Sg[r*65 + c];
    }
}

// ---------------------------------------------------------------------------
extern "C" void kernel_launch(void* const* d_in, const int* in_sizes, int n_in,
                              void* d_out, int out_size)
{
    const float* query = (const float*)d_in[0];
    const float* key   = (const float*)d_in[1];
    const float* value = (const float*)d_in[2];
    const float* Wq    = (const float*)d_in[3];
    const float* bq    = (const float*)d_in[4];
    const float* Wk    = (const float*)d_in[5];
    const float* bk    = (const float*)d_in[6];
    const float* Wv    = (const float*)d_in[7];
    const float* bv    = (const float*)d_in[8];
    const float* E_w   = (const float*)d_in[9];
    const float* E_b   = (const float*)d_in[10];
    const float* F_w   = (const float*)d_in[11];
    const float* F_b   = (const float*)d_in[12];
    const float* out_w = (const float*)d_in[13];
    const float* out_b = (const float*)d_in[14];

    const long long mha_elems  = (long long)NB*NS*NDM;
    const long long attn_elems = (long long)BH*NS*NT;

    float* outp = (float*)d_out;
    float* mha_ptr;
    float* attn_ptr;
    if ((long long)out_size >= mha_elems + attn_elems) {
        mha_ptr  = outp;
        attn_ptr = outp + mha_elems;
    } else if ((long long)out_size == attn_elems) {
        attn_ptr = outp;
        cudaGetSymbolAddress((void**)&mha_ptr, g_MHA_FB);
    } else {
        mha_ptr = outp;
        cudaGetSymbolAddress((void**)&attn_ptr, g_ATTN_FB);
    }

    __nv_bfloat16 *ewh, *ewl, *fwh, *fwl, *owh, *owl;
    cudaGetSymbolAddress((void**)&ewh, g_Ewh); cudaGetSymbolAddress((void**)&ewl, g_Ewl);
    cudaGetSymbolAddress((void**)&fwh, g_Fwh); cudaGetSymbolAddress((void**)&fwl, g_Fwl);
    cudaGetSymbolAddress((void**)&owh, g_Owh); cudaGetSymbolAddress((void**)&owl, g_Owl);

    cudaFuncSetAttribute(k_ke_mma,   cudaFuncAttributeMaxDynamicSharedMemorySize, 50688);
    cudaFuncSetAttribute(k_vf_mma,   cudaFuncAttributeMaxDynamicSharedMemorySize, 50688);
    cudaFuncSetAttribute(k_ho_mma,   cudaFuncAttributeMaxDynamicSharedMemorySize, 50688);
    cudaFuncSetAttribute(k_out_mma,  cudaFuncAttributeMaxDynamicSharedMemorySize, 50688);
    cudaFuncSetAttribute(k_attn_mma, cudaFuncAttributeMaxDynamicSharedMemorySize, 145664);

    k_qkv<<<dim3(BH, NS/64, 3), 256>>>(query, key, value, Wq, bq, Wk, bk, Wv, bv);
    k_split<<<(NT*NS + 255)/256, 256>>>(E_w, ewh, ewl, NT*NS);
    k_split<<<(NT*NS + 255)/256, 256>>>(F_w, fwh, fwl, NT*NS);
    k_split<<<(NDM*NDM + 255)/256, 256>>>(out_w, owh, owl, NDM*NDM);
    k_prep_kv<<<dim3(BH, NS/64, 2), 256>>>();
    k_ke_mma<<<dim3(BH, 4), 256, 50688>>>(E_b);
    k_vf_mma<<<dim3(BH, 4), 256, 50688>>>(F_b);
    k_attn_mma<<<dim3(BH, 16), 256, 145664>>>(attn_ptr);
    k_ho_mma<<<dim3(BH, 4), 256, 50688>>>(attn_ptr);
    k_out_mma<<<dim3((NB*NS)/128, NDM/64), 256, 50688>>>(out_b, mha_ptr);
}

// round 6
// speedup vs baseline: 1.7635x; 1.7635x over previous
#include <cuda_runtime.h>
#include <cuda_bf16.h>
#include <cstdint>

#define NB 32
#define NS 512
#define NH 16
#define NDH 64
#define NDM 1024
#define NT 512
#define BH (NB*NH)

// ---------------- global scratch ----------------
__device__ float g_K [BH*NS*NDH];
__device__ float g_V [BH*NS*NDH];
__device__ __nv_bfloat16 g_Qh [(size_t)BH*NS*NDH];
__device__ __nv_bfloat16 g_Ql [(size_t)BH*NS*NDH];
__device__ __nv_bfloat16 g_Kth[(size_t)BH*NDH*NS];
__device__ __nv_bfloat16 g_Ktl[(size_t)BH*NDH*NS];
__device__ __nv_bfloat16 g_Vth[(size_t)BH*NDH*NS];
__device__ __nv_bfloat16 g_Vtl[(size_t)BH*NDH*NS];
__device__ __nv_bfloat16 g_KEh[(size_t)BH*NT*NDH];
__device__ __nv_bfloat16 g_KEl[(size_t)BH*NT*NDH];
__device__ __nv_bfloat16 g_VFth[(size_t)BH*NDH*NT];
__device__ __nv_bfloat16 g_VFtl[(size_t)BH*NDH*NT];
__device__ __nv_bfloat16 g_Ewh[NT*NS], g_Ewl[NT*NS];
__device__ __nv_bfloat16 g_Fwh[NT*NS], g_Fwl[NT*NS];
__device__ __nv_bfloat16 g_Owh[NDM*NDM], g_Owl[NDM*NDM];
__device__ __nv_bfloat16 g_HOh[(size_t)BH*NS*NDH];
__device__ __nv_bfloat16 g_HOl[(size_t)BH*NS*NDH];
__device__ float g_ATTN_FB[(size_t)BH*NS*NT];
__device__ float g_MHA_FB [(size_t)NB*NS*NDM];

// ---------------- helpers ----------------
__device__ __forceinline__ uint32_t smem_u32(const void* p) {
    uint32_t a;
    asm("{ .reg .u64 t; cvta.to.shared.u64 t, %1; cvt.u32.u64 %0, t; }" : "=r"(a) : "l"(p));
    return a;
}
__device__ __forceinline__ void mma16816(float c[4],
                                         uint32_t a0, uint32_t a1, uint32_t a2, uint32_t a3,
                                         uint32_t b0, uint32_t b1)
{
    asm volatile(
        "mma.sync.aligned.m16n8k16.row.col.f32.bf16.bf16.f32 "
        "{%0,%1,%2,%3}, {%4,%5,%6,%7}, {%8,%9}, {%0,%1,%2,%3};"
        : "+f"(c[0]), "+f"(c[1]), "+f"(c[2]), "+f"(c[3])
        : "r"(a0), "r"(a1), "r"(a2), "r"(a3), "r"(b0), "r"(b1));
}
__device__ __forceinline__ void ldmx4(uint32_t& r0, uint32_t& r1, uint32_t& r2, uint32_t& r3,
                                      uint32_t addr)
{
    asm volatile("ldmatrix.sync.aligned.m8n8.x4.shared.b16 {%0,%1,%2,%3}, [%4];"
                 : "=r"(r0), "=r"(r1), "=r"(r2), "=r"(r3) : "r"(addr));
}
__device__ __forceinline__ void split2(float x, float y, uint32_t& hi, uint32_t& lo)
{
    __nv_bfloat162 h = __floats2bfloat162_rn(x, y);
    float hx = __bfloat162float(h.x), hy = __bfloat162float(h.y);
    __nv_bfloat162 l = __floats2bfloat162_rn(x - hx, y - hy);
    hi = *(uint32_t*)&h;
    lo = *(uint32_t*)&l;
}

// smem geometry for GEMM kernels (u32 units): row stride 36 (144B, 16B aligned)
// Ah@0 (128x36=4608) | Al@4608 | Bh@9216 (64x36=2304) | Bl@11520 | total 13824 u32
#define A_STRIDE_B 144
#define MI_STEP_B  2304   // 16 rows * 144
#define KS_STEP_B  32     // 8 words

// fragment-load + 3-term split MMA over one 64-k chunk (ks = 4 steps of 16)
#define MMA_CHUNK_LDSM()                                                          \
    _Pragma("unroll")                                                             \
    for (int ks = 0; ks < 4; ks++) {                                              \
        uint32_t ah[2][4], al[2][4];                                              \
        _Pragma("unroll")                                                         \
        for (int mi = 0; mi < 2; mi++) {                                          \
            ldmx4(ah[mi][0],ah[mi][1],ah[mi][2],ah[mi][3], aoffH + mi*MI_STEP_B + ks*KS_STEP_B); \
            ldmx4(al[mi][0],al[mi][1],al[mi][2],al[mi][3], aoffL + mi*MI_STEP_B + ks*KS_STEP_B); \
        }                                                                         \
        _Pragma("unroll")                                                         \
        for (int nj2 = 0; nj2 < 2; nj2++) {                                       \
            uint32_t bh[4], bl[4];                                                \
            ldmx4(bh[0],bh[1],bh[2],bh[3], boffH + nj2*MI_STEP_B + ks*KS_STEP_B); \
            ldmx4(bl[0],bl[1],bl[2],bl[3], boffL + nj2*MI_STEP_B + ks*KS_STEP_B); \
            _Pragma("unroll")                                                     \
            for (int jj = 0; jj < 2; jj++) {                                      \
                int nj = nj2*2 + jj;                                              \
                _Pragma("unroll")                                                 \
                for (int mi = 0; mi < 2; mi++) {                                  \
                    mma16816(acc[mi][nj], ah[mi][0],ah[mi][1],ah[mi][2],ah[mi][3], bh[jj], bh[jj+2]); \
                    mma16816(acc[mi][nj], ah[mi][0],ah[mi][1],ah[mi][2],ah[mi][3], bl[jj], bl[jj+2]); \
                    mma16816(acc[mi][nj], al[mi][0],al[mi][1],al[mi][2],al[mi][3], bh[jj], bh[jj+2]); \
                }                                                                 \
            }                                                                     \
        }                                                                         \
    }

// ---------------------------------------------------------------------------
// Kernel 1: per-head Q/K/V projection (fp32). Q written as bf16 split.
// ---------------------------------------------------------------------------
__global__ void k_qkv(const float* __restrict__ qin, const float* __restrict__ kin,
                      const float* __restrict__ vin,
                      const float* __restrict__ Wq, const float* __restrict__ bq,
                      const float* __restrict__ Wk, const float* __restrict__ bk,
                      const float* __restrict__ Wv, const float* __restrict__ bv)
{
    __shared__ float WT[64][65];
    __shared__ float Xs[64][64];
    int bh = blockIdx.x;
    int b  = bh >> 4, h = bh & 15;
    int s0 = blockIdx.y << 6;
    const float *in, *W, *bias; float* out = nullptr;
    if (blockIdx.z == 0)      { in = qin; W = Wq; bias = bq; }
    else if (blockIdx.z == 1) { in = kin; W = Wk; bias = bk; out = g_K; }
    else                      { in = vin; W = Wv; bias = bv; out = g_V; }
    int tid = threadIdx.x;
    for (int i = tid; i < 4096; i += 256) {
        int r = i >> 6, c = i & 63;
        WT[c][r] = W[(h*64 + r)*64 + c];
        Xs[r][c] = in[((b*NS) + s0 + r)*64 + c];
    }
    __syncthreads();
    int e  = tid & 63;
    int ty = tid >> 6;
    float bval = bias[h*64 + e];
    float acc[16];
#pragma unroll
    for (int j = 0; j < 16; j++) acc[j] = bval;
#pragma unroll 4
    for (int d = 0; d < 64; d++) {
        float w = WT[d][e];
#pragma unroll
        for (int j = 0; j < 16; j++) acc[j] += Xs[ty + j*4][d] * w;
    }
    if (blockIdx.z == 0) {
#pragma unroll
        for (int j = 0; j < 16; j++) {
            size_t idx = ((size_t)bh*NS + s0 + ty + j*4)*64 + e;
            __nv_bfloat16 hb = __float2bfloat16(acc[j]);
            g_Qh[idx] = hb;
            g_Ql[idx] = __float2bfloat16(acc[j] - __bfloat162float(hb));
        }
    } else {
#pragma unroll
        for (int j = 0; j < 16; j++)
            out[((size_t)bh*NS + s0 + ty + j*4)*64 + e] = acc[j];
    }
}

__global__ void k_split(const float* __restrict__ s, __nv_bfloat16* __restrict__ h,
                        __nv_bfloat16* __restrict__ l, int n)
{
    int i = blockIdx.x * 256 + threadIdx.x;
    if (i < n) {
        float v = s[i];
        __nv_bfloat16 hb = __float2bfloat16(v);
        h[i] = hb;
        l[i] = __float2bfloat16(v - __bfloat162float(hb));
    }
}

__global__ void k_prep_kv()
{
    __shared__ float ts[64][65];
    int bh = blockIdx.x, s0 = blockIdx.y << 6;
    const float* src = (blockIdx.z == 0 ? g_K : g_V) + (size_t)bh*NS*NDH;
    __nv_bfloat16* dh = (blockIdx.z == 0 ? g_Kth : g_Vth) + (size_t)bh*NDH*NS;
    __nv_bfloat16* dl = (blockIdx.z == 0 ? g_Ktl : g_Vtl) + (size_t)bh*NDH*NS;
    int tid = threadIdx.x;
    for (int i = tid; i < 4096; i += 256) {
        int r = i >> 6, c = i & 63;
        ts[r][c] = src[(s0 + r)*64 + c];
    }
    __syncthreads();
    for (int i = tid; i < 4096; i += 256) {
        int d = i >> 6, r = i & 63;
        float v = ts[r][d];
        __nv_bfloat16 hb = __float2bfloat16(v);
        dh[(size_t)d*NS + s0 + r] = hb;
        dl[(size_t)d*NS + s0 + r] = __float2bfloat16(v - __bfloat162float(hb));
    }
}

// ---------------------------------------------------------------------------
// k_ke_mma: D[t(128)][d(64)] = sum_s Ew[t][s]*Kt[d][s] + Eb[t] -> KE split [bh][t][d]
// grid (BH, 4), block 256, dyn smem 55296
// ---------------------------------------------------------------------------
__global__ void __launch_bounds__(256, 2) k_ke_mma(const float* __restrict__ Eb)
{
    extern __shared__ uint32_t sm32[];
    int tid = threadIdx.x, wid = tid >> 5, lane = tid & 31;
    int g = lane >> 2, t4 = lane & 3;
    int m0w = (wid & 3)*32, n0w = (wid >> 2)*32;
    int bh = blockIdx.x, t0 = blockIdx.y << 7;

    uint32_t sb = smem_u32(sm32);
    uint32_t lrow = lane & 15, lsel = (lane >> 4) << 4;
    uint32_t aoffH = sb + (m0w + lrow)*A_STRIDE_B + lsel;
    uint32_t aoffL = aoffH + 18432;
    uint32_t boffH = sb + 36864 + (n0w + lrow)*A_STRIDE_B + lsel;
    uint32_t boffL = boffH + 9216;

    float acc[2][4][4];
#pragma unroll
    for (int mi = 0; mi < 2; mi++)
#pragma unroll
        for (int nj = 0; nj < 4; nj++)
#pragma unroll
            for (int q = 0; q < 4; q++) acc[mi][nj][q] = 0.f;

    const uint4* gA4h = (const uint4*)(g_Ewh + (size_t)t0*NS);
    const uint4* gA4l = (const uint4*)(g_Ewl + (size_t)t0*NS);
    const uint4* gB4h = (const uint4*)(g_Kth + (size_t)bh*NDH*NS);
    const uint4* gB4l = (const uint4*)(g_Ktl + (size_t)bh*NDH*NS);

    for (int ch = 0; ch < 8; ch++) {
        __syncthreads();
        for (int i = tid; i < 1024; i += 256) {
            int r = i >> 3, c = i & 7;
            *(uint4*)&sm32[r*36 + c*4]        = gA4h[(size_t)r*64 + ch*8 + c];
            *(uint4*)&sm32[4608 + r*36 + c*4] = gA4l[(size_t)r*64 + ch*8 + c];
        }
        for (int i = tid; i < 512; i += 256) {
            int r = i >> 3, c = i & 7;
            *(uint4*)&sm32[9216 + r*36 + c*4]  = gB4h[(size_t)r*64 + ch*8 + c];
            *(uint4*)&sm32[11520 + r*36 + c*4] = gB4l[(size_t)r*64 + ch*8 + c];
        }
        __syncthreads();
        MMA_CHUNK_LDSM();
    }

    size_t base = (size_t)bh*NT*NDH;
#pragma unroll
    for (int mi = 0; mi < 2; mi++) {
        int m = m0w + mi*16 + g;
        float e0 = Eb[t0 + m];
        float e1 = Eb[t0 + m + 8];
#pragma unroll
        for (int nj = 0; nj < 4; nj++) {
            int n = n0w + nj*8 + t4*2;
            uint32_t hi, lo;
            size_t i0 = base + (size_t)(t0 + m)*NDH + n;
            split2(acc[mi][nj][0] + e0, acc[mi][nj][1] + e0, hi, lo);
            *(uint32_t*)(g_KEh + i0) = hi;  *(uint32_t*)(g_KEl + i0) = lo;
            size_t i1 = base + (size_t)(t0 + m + 8)*NDH + n;
            split2(acc[mi][nj][2] + e1, acc[mi][nj][3] + e1, hi, lo);
            *(uint32_t*)(g_KEh + i1) = hi;  *(uint32_t*)(g_KEl + i1) = lo;
        }
    }
}

// ---------------------------------------------------------------------------
// k_vf_mma: D[t(128)][d(64)] = sum_s Fw[t][s]*Vt[d][s] + Fb[t] -> VF^T split [bh][d][t]
// ---------------------------------------------------------------------------
__global__ void __launch_bounds__(256, 2) k_vf_mma(const float* __restrict__ Fb)
{
    extern __shared__ uint32_t sm32[];
    int tid = threadIdx.x, wid = tid >> 5, lane = tid & 31;
    int g = lane >> 2, t4 = lane & 3;
    int m0w = (wid & 3)*32, n0w = (wid >> 2)*32;
    int bh = blockIdx.x, t0 = blockIdx.y << 7;

    uint32_t sb = smem_u32(sm32);
    uint32_t lrow = lane & 15, lsel = (lane >> 4) << 4;
    uint32_t aoffH = sb + (m0w + lrow)*A_STRIDE_B + lsel;
    uint32_t aoffL = aoffH + 18432;
    uint32_t boffH = sb + 36864 + (n0w + lrow)*A_STRIDE_B + lsel;
    uint32_t boffL = boffH + 9216;

    float acc[2][4][4];
#pragma unroll
    for (int mi = 0; mi < 2; mi++)
#pragma unroll
        for (int nj = 0; nj < 4; nj++)
#pragma unroll
            for (int q = 0; q < 4; q++) acc[mi][nj][q] = 0.f;

    const uint4* gA4h = (const uint4*)(g_Fwh + (size_t)t0*NS);
    const uint4* gA4l = (const uint4*)(g_Fwl + (size_t)t0*NS);
    const uint4* gB4h = (const uint4*)(g_Vth + (size_t)bh*NDH*NS);
    const uint4* gB4l = (const uint4*)(g_Vtl + (size_t)bh*NDH*NS);

    for (int ch = 0; ch < 8; ch++) {
        __syncthreads();
        for (int i = tid; i < 1024; i += 256) {
            int r = i >> 3, c = i & 7;
            *(uint4*)&sm32[r*36 + c*4]        = gA4h[(size_t)r*64 + ch*8 + c];
            *(uint4*)&sm32[4608 + r*36 + c*4] = gA4l[(size_t)r*64 + ch*8 + c];
        }
        for (int i = tid; i < 512; i += 256) {
            int r = i >> 3, c = i & 7;
            *(uint4*)&sm32[9216 + r*36 + c*4]  = gB4h[(size_t)r*64 + ch*8 + c];
            *(uint4*)&sm32[11520 + r*36 + c*4] = gB4l[(size_t)r*64 + ch*8 + c];
        }
        __syncthreads();
        MMA_CHUNK_LDSM();
    }

    // stage transposed [d][t] fp32 (+Fb), then split-store rows of VF^T
    __syncthreads();
    float* Sg = (float*)sm32;          // [64][129]
#pragma unroll
    for (int mi = 0; mi < 2; mi++) {
        int m = m0w + mi*16 + g;
        float f0 = Fb[t0 + m];
        float f1 = Fb[t0 + m + 8];
#pragma unroll
        for (int nj = 0; nj < 4; nj++) {
            int n = n0w + nj*8 + t4*2;
            Sg[n*129 + m]         = acc[mi][nj][0] + f0;
            Sg[(n+1)*129 + m]     = acc[mi][nj][1] + f0;
            Sg[n*129 + m + 8]     = acc[mi][nj][2] + f1;
            Sg[(n+1)*129 + m + 8] = acc[mi][nj][3] + f1;
        }
    }
    __syncthreads();
    size_t base = (size_t)bh*NDH*NT;
    for (int i = tid; i < 4096; i += 256) {
        int d = i >> 6, mm = (i & 63)*2;
        uint32_t hi, lo;
        split2(Sg[d*129 + mm], Sg[d*129 + mm + 1], hi, lo);
        size_t idx = base + (size_t)d*NT + t0 + mm;
        *(uint32_t*)(g_VFth + idx) = hi;
        *(uint32_t*)(g_VFtl + idx) = lo;
    }
}

// ---------------------------------------------------------------------------
// k_attn_mma: scores = 0.125 * Q·KE^T, softmax, write attn.
// grid (BH, 16), block 256. KE chunked 2x256 -> smem 84992 B -> occupancy 2.
// smem u32: KEh@0 (256x36=9216) | KEl@9216 | Qh@18432 (32x36=1152) | Ql@19584 |
//           redm@20736 (256 f32) | reds@20992 | total 21248 u32
// ---------------------------------------------------------------------------
__global__ void __launch_bounds__(256, 2) k_attn_mma(float* __restrict__ attn_out)
{
    extern __shared__ uint32_t sm32[];
    float* sredm = (float*)(sm32 + 20736);
    float* sreds = (float*)(sm32 + 20992);
    int tid = threadIdx.x, wid = tid >> 5, lane = tid & 31;
    int g = lane >> 2, t4 = lane & 3;
    int bh = blockIdx.x, s0 = blockIdx.y << 5;

    uint32_t sb = smem_u32(sm32);
    uint32_t lrow = lane & 15, lsel = (lane >> 4) << 4;
    uint32_t aoffH = sb + 73728 + lrow*A_STRIDE_B + lsel;        // Qh @18432 u32
    uint32_t aoffL = aoffH + 4608;                               // Ql @19584 u32
    uint32_t boffH = sb + (wid*32 + lrow)*A_STRIDE_B + lsel;     // KEh @0
    uint32_t boffL = boffH + 36864;                              // KEl @9216 u32

    // load Q tile (32 rows x 8 uint4)
    const uint4* gQ4h = (const uint4*)(g_Qh + ((size_t)bh*NS + s0)*NDH);
    const uint4* gQ4l = (const uint4*)(g_Ql + ((size_t)bh*NS + s0)*NDH);
    {
        int r = tid >> 3, c = tid & 7;
        *(uint4*)&sm32[18432 + r*36 + c*4] = gQ4h[(size_t)r*8 + c];
        *(uint4*)&sm32[19584 + r*36 + c*4] = gQ4l[(size_t)r*8 + c];
    }

    float acc[2][8][4];
#pragma unroll
    for (int mi = 0; mi < 2; mi++)
#pragma unroll
        for (int nj = 0; nj < 8; nj++)
#pragma unroll
            for (int q = 0; q < 4; q++) acc[mi][nj][q] = 0.f;

    const uint4* gKE4h = (const uint4*)(g_KEh + (size_t)bh*NT*NDH);
    const uint4* gKE4l = (const uint4*)(g_KEl + (size_t)bh*NT*NDH);

    for (int chn = 0; chn < 2; chn++) {
        if (chn) __syncthreads();
        for (int i = tid; i < 2048; i += 256) {
            int r = i >> 3, c = i & 7;
            *(uint4*)&sm32[r*36 + c*4]        = gKE4h[(size_t)(chn*256 + r)*8 + c];
            *(uint4*)&sm32[9216 + r*36 + c*4] = gKE4l[(size_t)(chn*256 + r)*8 + c];
        }
        __syncthreads();
#pragma unroll
        for (int ks = 0; ks < 4; ks++) {
            uint32_t ah[2][4], al[2][4];
#pragma unroll
            for (int mi = 0; mi < 2; mi++) {
                ldmx4(ah[mi][0],ah[mi][1],ah[mi][2],ah[mi][3], aoffH + mi*MI_STEP_B + ks*KS_STEP_B);
                ldmx4(al[mi][0],al[mi][1],al[mi][2],al[mi][3], aoffL + mi*MI_STEP_B + ks*KS_STEP_B);
            }
#pragma unroll
            for (int nj2 = 0; nj2 < 2; nj2++) {
                uint32_t bhp[4], blp[4];
                ldmx4(bhp[0],bhp[1],bhp[2],bhp[3], boffH + nj2*MI_STEP_B + ks*KS_STEP_B);
                ldmx4(blp[0],blp[1],blp[2],blp[3], boffL + nj2*MI_STEP_B + ks*KS_STEP_B);
#pragma unroll
                for (int jj = 0; jj < 2; jj++) {
                    int nj = chn*4 + nj2*2 + jj;
#pragma unroll
                    for (int mi = 0; mi < 2; mi++) {
                        mma16816(acc[mi][nj], ah[mi][0],ah[mi][1],ah[mi][2],ah[mi][3], bhp[jj], bhp[jj+2]);
                        mma16816(acc[mi][nj], ah[mi][0],ah[mi][1],ah[mi][2],ah[mi][3], blp[jj], blp[jj+2]);
                        mma16816(acc[mi][nj], al[mi][0],al[mi][1],al[mi][2],al[mi][3], bhp[jj], bhp[jj+2]);
                    }
                }
            }
        }
    }

    // scale + warp-local row max
    float lm[2][2];
#pragma unroll
    for (int mi = 0; mi < 2; mi++) { lm[mi][0] = -1e30f; lm[mi][1] = -1e30f; }
#pragma unroll
    for (int mi = 0; mi < 2; mi++)
#pragma unroll
        for (int nj = 0; nj < 8; nj++) {
#pragma unroll
            for (int q = 0; q < 4; q++) acc[mi][nj][q] *= 0.125f;
            lm[mi][0] = fmaxf(lm[mi][0], fmaxf(acc[mi][nj][0], acc[mi][nj][1]));
            lm[mi][1] = fmaxf(lm[mi][1], fmaxf(acc[mi][nj][2], acc[mi][nj][3]));
        }
#pragma unroll
    for (int mi = 0; mi < 2; mi++)
#pragma unroll
        for (int hh = 0; hh < 2; hh++) {
            lm[mi][hh] = fmaxf(lm[mi][hh], __shfl_xor_sync(0xffffffffu, lm[mi][hh], 1));
            lm[mi][hh] = fmaxf(lm[mi][hh], __shfl_xor_sync(0xffffffffu, lm[mi][hh], 2));
        }
    if (t4 == 0) {
#pragma unroll
        for (int mi = 0; mi < 2; mi++) {
            sredm[wid*32 + mi*16 + g]     = lm[mi][0];
            sredm[wid*32 + mi*16 + g + 8] = lm[mi][1];
        }
    }
    __syncthreads();
    float rowm[2][2];
#pragma unroll
    for (int mi = 0; mi < 2; mi++)
#pragma unroll
        for (int hh = 0; hh < 2; hh++) {
            int row = mi*16 + g + hh*8;
            float m = sredm[row];
#pragma unroll
            for (int w = 1; w < 8; w++) m = fmaxf(m, sredm[w*32 + row]);
            rowm[mi][hh] = m;
        }

    float ls[2][2] = {{0.f,0.f},{0.f,0.f}};
#pragma unroll
    for (int mi = 0; mi < 2; mi++)
#pragma unroll
        for (int nj = 0; nj < 8; nj++) {
            acc[mi][nj][0] = __expf(acc[mi][nj][0] - rowm[mi][0]);
            acc[mi][nj][1] = __expf(acc[mi][nj][1] - rowm[mi][0]);
            acc[mi][nj][2] = __expf(acc[mi][nj][2] - rowm[mi][1]);
            acc[mi][nj][3] = __expf(acc[mi][nj][3] - rowm[mi][1]);
            ls[mi][0] += acc[mi][nj][0] + acc[mi][nj][1];
            ls[mi][1] += acc[mi][nj][2] + acc[mi][nj][3];
        }
#pragma unroll
    for (int mi = 0; mi < 2; mi++)
#pragma unroll
        for (int hh = 0; hh < 2; hh++) {
            ls[mi][hh] += __shfl_xor_sync(0xffffffffu, ls[mi][hh], 1);
            ls[mi][hh] += __shfl_xor_sync(0xffffffffu, ls[mi][hh], 2);
        }
    if (t4 == 0) {
#pragma unroll
        for (int mi = 0; mi < 2; mi++) {
            sreds[wid*32 + mi*16 + g]     = ls[mi][0];
            sreds[wid*32 + mi*16 + g + 8] = ls[mi][1];
        }
    }
    __syncthreads();
    float inv[2][2];
#pragma unroll
    for (int mi = 0; mi < 2; mi++)
#pragma unroll
        for (int hh = 0; hh < 2; hh++) {
            int row = mi*16 + g + hh*8;
            float s = 0.f;
#pragma unroll
            for (int w = 0; w < 8; w++) s += sreds[w*32 + row];
            inv[mi][hh] = 1.f / s;
        }

#pragma unroll
    for (int mi = 0; mi < 2; mi++) {
        size_t r0 = ((size_t)bh*NS + s0 + mi*16 + g)*NT;
        size_t r1 = r0 + 8*NT;
#pragma unroll
        for (int nj = 0; nj < 8; nj++) {
            int col = (nj >> 2)*256 + wid*32 + (nj & 3)*8 + 2*t4;
            float2 v0 = make_float2(acc[mi][nj][0]*inv[mi][0], acc[mi][nj][1]*inv[mi][0]);
            float2 v1 = make_float2(acc[mi][nj][2]*inv[mi][1], acc[mi][nj][3]*inv[mi][1]);
            *(float2*)(attn_out + r0 + col) = v0;
            *(float2*)(attn_out + r1 + col) = v1;
        }
    }
}

// ---------------------------------------------------------------------------
// k_ho_mma: HO[s(128)][d(64)] = sum_t attn[s][t]*VFt[d][t]  (A split on-the-fly)
// ---------------------------------------------------------------------------
__global__ void __launch_bounds__(256, 2) k_ho_mma(const float* __restrict__ attn)
{
    extern __shared__ uint32_t sm32[];
    int tid = threadIdx.x, wid = tid >> 5, lane = tid & 31;
    int g = lane >> 2, t4 = lane & 3;
    int m0w = (wid & 3)*32, n0w = (wid >> 2)*32;
    int bh = blockIdx.x, s0 = blockIdx.y << 7;

    uint32_t sb = smem_u32(sm32);
    uint32_t lrow = lane & 15, lsel = (lane >> 4) << 4;
    uint32_t aoffH = sb + (m0w + lrow)*A_STRIDE_B + lsel;
    uint32_t aoffL = aoffH + 18432;
    uint32_t boffH = sb + 36864 + (n0w + lrow)*A_STRIDE_B + lsel;
    uint32_t boffL = boffH + 9216;

    float acc[2][4][4];
#pragma unroll
    for (int mi = 0; mi < 2; mi++)
#pragma unroll
        for (int nj = 0; nj < 4; nj++)
#pragma unroll
            for (int q = 0; q < 4; q++) acc[mi][nj][q] = 0.f;

    const float* gA = attn + ((size_t)bh*NS + s0)*NT;
    const uint4* gB4h = (const uint4*)(g_VFth + (size_t)bh*NDH*NT);
    const uint4* gB4l = (const uint4*)(g_VFtl + (size_t)bh*NDH*NT);

    for (int ch = 0; ch < 8; ch++) {
        __syncthreads();
        for (int i = tid; i < 1024; i += 256) {
            int r = i >> 3, c = i & 7;
            const float4* src = (const float4*)(gA + (size_t)r*NT + ch*64 + c*8);
            float4 x = src[0], y = src[1];
            uint32_t h0,l0,h1,l1,h2,l2,h3,l3;
            split2(x.x, x.y, h0, l0); split2(x.z, x.w, h1, l1);
            split2(y.x, y.y, h2, l2); split2(y.z, y.w, h3, l3);
            *(uint4*)&sm32[r*36 + c*4]        = make_uint4(h0,h1,h2,h3);
            *(uint4*)&sm32[4608 + r*36 + c*4] = make_uint4(l0,l1,l2,l3);
        }
        for (int i = tid; i < 512; i += 256) {
            int r = i >> 3, c = i & 7;
            *(uint4*)&sm32[9216 + r*36 + c*4]  = gB4h[(size_t)r*64 + ch*8 + c];
            *(uint4*)&sm32[11520 + r*36 + c*4] = gB4l[(size_t)r*64 + ch*8 + c];
        }
        __syncthreads();
        MMA_CHUNK_LDSM();
    }

    size_t base = (size_t)bh*NS*NDH;
#pragma unroll
    for (int mi = 0; mi < 2; mi++) {
        int m = m0w + mi*16 + g;
#pragma unroll
        for (int nj = 0; nj < 4; nj++) {
            int n = n0w + nj*8 + t4*2;
            uint32_t hi, lo;
            size_t i0 = base + (size_t)(s0 + m)*NDH + n;
            split2(acc[mi][nj][0], acc[mi][nj][1], hi, lo);
            *(uint32_t*)(g_HOh + i0) = hi;  *(uint32_t*)(g_HOl + i0) = lo;
            size_t i1 = base + (size_t)(s0 + m + 8)*NDH + n;
            split2(acc[mi][nj][2], acc[mi][nj][3], hi, lo);
            *(uint32_t*)(g_HOh + i1) = hi;  *(uint32_t*)(g_HOl + i1) = lo;
        }
    }
}

// ---------------------------------------------------------------------------
// k_out_mma: out[m(128)][n(64)] = sum_k HO[m][k]*Ow[n][k] + Ob[n]
// ---------------------------------------------------------------------------
__global__ void __launch_bounds__(256, 2) k_out_mma(const float* __restrict__ Ob,
                                                    float* __restrict__ out)
{
    extern __shared__ uint32_t sm32[];
    int tid = threadIdx.x, wid = tid >> 5, lane = tid & 31;
    int g = lane >> 2, t4 = lane & 3;
    int m0w = (wid & 3)*32, n0w = (wid >> 2)*32;
    int m0 = blockIdx.x << 7;
    int b  = blockIdx.x >> 2;
    int sbase = (blockIdx.x & 3) << 7;
    int n0 = blockIdx.y << 6;

    uint32_t sb = smem_u32(sm32);
    uint32_t lrow = lane & 15, lsel = (lane >> 4) << 4;
    uint32_t aoffH = sb + (m0w + lrow)*A_STRIDE_B + lsel;
    uint32_t aoffL = aoffH + 18432;
    uint32_t boffH = sb + 36864 + (n0w + lrow)*A_STRIDE_B + lsel;
    uint32_t boffL = boffH + 9216;

    float acc[2][4][4];
#pragma unroll
    for (int mi = 0; mi < 2; mi++)
#pragma unroll
        for (int nj = 0; nj < 4; nj++)
#pragma unroll
            for (int q = 0; q < 4; q++) acc[mi][nj][q] = 0.f;

    for (int kc = 0; kc < 16; kc++) {
        const uint4* gA4h = (const uint4*)(g_HOh + ((size_t)(b*NH + kc)*NS + sbase)*NDH);
        const uint4* gA4l = (const uint4*)(g_HOl + ((size_t)(b*NH + kc)*NS + sbase)*NDH);
        const uint4* gB4h = (const uint4*)(g_Owh + (size_t)n0*NDM);
        const uint4* gB4l = (const uint4*)(g_Owl + (size_t)n0*NDM);
        __syncthreads();
        for (int i = tid; i < 1024; i += 256) {
            int r = i >> 3, c = i & 7;
            *(uint4*)&sm32[r*36 + c*4]        = gA4h[(size_t)r*8 + c];
            *(uint4*)&sm32[4608 + r*36 + c*4] = gA4l[(size_t)r*8 + c];
        }
        for (int i = tid; i < 512; i += 256) {
            int r = i >> 3, c = i & 7;
            *(uint4*)&sm32[9216 + r*36 + c*4]  = gB4h[(size_t)r*128 + kc*8 + c];
            *(uint4*)&sm32[11520 + r*36 + c*4] = gB4l[(size_t)r*128 + kc*8 + c];
        }
        __syncthreads();
        MMA_CHUNK_LDSM();
    }

    __syncthreads();
    float* Sg = (float*)sm32;          // [128][65]
#pragma unroll
    for (int mi = 0; mi < 2; mi++) {
        int m = m0w + mi*16 + g;
#pragma unroll
        for (int nj = 0; nj < 4; nj++) {
            int n = n0w + nj*8 + t4*2;
            float o0 = Ob[n0 + n];
            float o1 = Ob[n0 + n + 1];
            Sg[m*65 + n]         = acc[mi][nj][0] + o0;
            Sg[m*65 + n + 1]     = acc[mi][nj][1] + o1;
            Sg[(m+8)*65 + n]     = acc[mi][nj][2] + o0;
            Sg[(m+8)*65 + n + 1] = acc[mi][nj][3] + o1;
        }
    }
    __syncthreads();
    for (int i = tid; i < 8192; i += 256) {
        int r = i >> 6, c = i & 63;
        out[(size_t)(m0 + r)*NDM + n0 + c] = Sg[r*65 + c];
    }
}

// ---------------------------------------------------------------------------
extern "C" void kernel_launch(void* const* d_in, const int* in_sizes, int n_in,
                              void* d_out, int out_size)
{
    const float* query = (const float*)d_in[0];
    const float* key   = (const float*)d_in[1];
    const float* value = (const float*)d_in[2];
    const float* Wq    = (const float*)d_in[3];
    const float* bq    = (const float*)d_in[4];
    const float* Wk    = (const float*)d_in[5];
    const float* bk    = (const float*)d_in[6];
    const float* Wv    = (const float*)d_in[7];
    const float* bv    = (const float*)d_in[8];
    const float* E_w   = (const float*)d_in[9];
    const float* E_b   = (const float*)d_in[10];
    const float* F_w   = (const float*)d_in[11];
    const float* F_b   = (const float*)d_in[12];
    const float* out_w = (const float*)d_in[13];
    const float* out_b = (const float*)d_in[14];

    const long long mha_elems  = (long long)NB*NS*NDM;
    const long long attn_elems = (long long)BH*NS*NT;

    float* outp = (float*)d_out;
    float* mha_ptr;
    float* attn_ptr;
    if ((long long)out_size >= mha_elems + attn_elems) {
        mha_ptr  = outp;
        attn_ptr = outp + mha_elems;
    } else if ((long long)out_size == attn_elems) {
        attn_ptr = outp;
        cudaGetSymbolAddress((void**)&mha_ptr, g_MHA_FB);
    } else {
        mha_ptr = outp;
        cudaGetSymbolAddress((void**)&attn_ptr, g_ATTN_FB);
    }

    __nv_bfloat16 *ewh, *ewl, *fwh, *fwl, *owh, *owl;
    cudaGetSymbolAddress((void**)&ewh, g_Ewh); cudaGetSymbolAddress((void**)&ewl, g_Ewl);
    cudaGetSymbolAddress((void**)&fwh, g_Fwh); cudaGetSymbolAddress((void**)&fwl, g_Fwl);
    cudaGetSymbolAddress((void**)&owh, g_Owh); cudaGetSymbolAddress((void**)&owl, g_Owl);

    cudaFuncSetAttribute(k_ke_mma,   cudaFuncAttributeMaxDynamicSharedMemorySize, 55296);
    cudaFuncSetAttribute(k_vf_mma,   cudaFuncAttributeMaxDynamicSharedMemorySize, 55296);
    cudaFuncSetAttribute(k_ho_mma,   cudaFuncAttributeMaxDynamicSharedMemorySize, 55296);
    cudaFuncSetAttribute(k_out_mma,  cudaFuncAttributeMaxDynamicSharedMemorySize, 55296);
    cudaFuncSetAttribute(k_attn_mma, cudaFuncAttributeMaxDynamicSharedMemorySize, 84992);

    k_qkv<<<dim3(BH, NS/64, 3), 256>>>(query, key, value, Wq, bq, Wk, bk, Wv, bv);
    k_split<<<(NT*NS + 255)/256, 256>>>(E_w, ewh, ewl, NT*NS);
    k_split<<<(NT*NS + 255)/256, 256>>>(F_w, fwh, fwl, NT*NS);
    k_split<<<(NDM*NDM + 255)/256, 256>>>(out_w, owh, owl, NDM*NDM);
    k_prep_kv<<<dim3(BH, NS/64, 2), 256>>>();
    k_ke_mma<<<dim3(BH, 4), 256, 55296>>>(E_b);
    k_vf_mma<<<dim3(BH, 4), 256, 55296>>>(F_b);
    k_attn_mma<<<dim3(BH, 16), 256, 84992>>>(attn_ptr);
    k_ho_mma<<<dim3(BH, 4), 256, 55296>>>(attn_ptr);
    k_out_mma<<<dim3((NB*NS)/128, NDM/64), 256, 55296>>>(out_b, mha_ptr);
}

// round 7
// speedup vs baseline: 1.8323x; 1.0390x over previous
#include <cuda_runtime.h>
#include <cuda_bf16.h>
#include <cstdint>

#define NB 32
#define NS 512
#define NH 16
#define NDH 64
#define NDM 1024
#define NT 512
#define BH (NB*NH)

// ---------------- global scratch ----------------
__device__ __nv_bfloat16 g_Xqh[NB*NS*NDH], g_Xql[NB*NS*NDH];
__device__ __nv_bfloat16 g_Xkh[NB*NS*NDH], g_Xkl[NB*NS*NDH];
__device__ __nv_bfloat16 g_Xvh[NB*NS*NDH], g_Xvl[NB*NS*NDH];
__device__ __nv_bfloat16 g_Wqh[NH*NDH*NDH], g_Wql[NH*NDH*NDH];
__device__ __nv_bfloat16 g_Wkh[NH*NDH*NDH], g_Wkl[NH*NDH*NDH];
__device__ __nv_bfloat16 g_Wvh[NH*NDH*NDH], g_Wvl[NH*NDH*NDH];
__device__ __nv_bfloat16 g_Qh [(size_t)BH*NS*NDH];
__device__ __nv_bfloat16 g_Ql [(size_t)BH*NS*NDH];
__device__ __nv_bfloat16 g_Kth[(size_t)BH*NDH*NS];
__device__ __nv_bfloat16 g_Ktl[(size_t)BH*NDH*NS];
__device__ __nv_bfloat16 g_Vth[(size_t)BH*NDH*NS];
__device__ __nv_bfloat16 g_Vtl[(size_t)BH*NDH*NS];
__device__ __nv_bfloat16 g_KEh[(size_t)BH*NT*NDH];
__device__ __nv_bfloat16 g_KEl[(size_t)BH*NT*NDH];
__device__ __nv_bfloat16 g_VFth[(size_t)BH*NDH*NT];
__device__ __nv_bfloat16 g_VFtl[(size_t)BH*NDH*NT];
__device__ __nv_bfloat16 g_Ewh[NT*NS], g_Ewl[NT*NS];
__device__ __nv_bfloat16 g_Fwh[NT*NS], g_Fwl[NT*NS];
__device__ __nv_bfloat16 g_Owh[NDM*NDM], g_Owl[NDM*NDM];
__device__ __nv_bfloat16 g_HOh[(size_t)BH*NS*NDH];
__device__ __nv_bfloat16 g_HOl[(size_t)BH*NS*NDH];
__device__ float g_ATTN_FB[(size_t)BH*NS*NT];
__device__ float g_MHA_FB [(size_t)NB*NS*NDM];

// ---------------- helpers ----------------
__device__ __forceinline__ uint32_t smem_u32(const void* p) {
    uint32_t a;
    asm("{ .reg .u64 t; cvta.to.shared.u64 t, %1; cvt.u32.u64 %0, t; }" : "=r"(a) : "l"(p));
    return a;
}
__device__ __forceinline__ void mma16816(float c[4],
                                         uint32_t a0, uint32_t a1, uint32_t a2, uint32_t a3,
                                         uint32_t b0, uint32_t b1)
{
    asm volatile(
        "mma.sync.aligned.m16n8k16.row.col.f32.bf16.bf16.f32 "
        "{%0,%1,%2,%3}, {%4,%5,%6,%7}, {%8,%9}, {%0,%1,%2,%3};"
        : "+f"(c[0]), "+f"(c[1]), "+f"(c[2]), "+f"(c[3])
        : "r"(a0), "r"(a1), "r"(a2), "r"(a3), "r"(b0), "r"(b1));
}
__device__ __forceinline__ void ldmx4(uint32_t& r0, uint32_t& r1, uint32_t& r2, uint32_t& r3,
                                      uint32_t addr)
{
    asm volatile("ldmatrix.sync.aligned.m8n8.x4.shared.b16 {%0,%1,%2,%3}, [%4];"
                 : "=r"(r0), "=r"(r1), "=r"(r2), "=r"(r3) : "r"(addr));
}
__device__ __forceinline__ void split2(float x, float y, uint32_t& hi, uint32_t& lo)
{
    __nv_bfloat162 h = __floats2bfloat162_rn(x, y);
    float hx = __bfloat162float(h.x), hy = __bfloat162float(h.y);
    __nv_bfloat162 l = __floats2bfloat162_rn(x - hx, y - hy);
    hi = *(uint32_t*)&h;
    lo = *(uint32_t*)&l;
}

// smem geometry (u32 units): row stride 36 words (144B)
// Ah@0 (128x36) | Al@4608 | Bh@9216 (64x36) | Bl@11520 | total 13824 u32
#define A_STRIDE_B 144
#define MI_STEP_B  2304
#define KS_STEP_B  32

#define MMA_CHUNK_LDSM()                                                          \
    _Pragma("unroll")                                                             \
    for (int ks = 0; ks < 4; ks++) {                                              \
        uint32_t ah[2][4], al[2][4];                                              \
        _Pragma("unroll")                                                         \
        for (int mi = 0; mi < 2; mi++) {                                          \
            ldmx4(ah[mi][0],ah[mi][1],ah[mi][2],ah[mi][3], aoffH + mi*MI_STEP_B + ks*KS_STEP_B); \
            ldmx4(al[mi][0],al[mi][1],al[mi][2],al[mi][3], aoffL + mi*MI_STEP_B + ks*KS_STEP_B); \
        }                                                                         \
        _Pragma("unroll")                                                         \
        for (int nj2 = 0; nj2 < 2; nj2++) {                                       \
            uint32_t bh[4], bl[4];                                                \
            ldmx4(bh[0],bh[1],bh[2],bh[3], boffH + nj2*MI_STEP_B + ks*KS_STEP_B); \
            ldmx4(bl[0],bl[1],bl[2],bl[3], boffL + nj2*MI_STEP_B + ks*KS_STEP_B); \
            _Pragma("unroll")                                                     \
            for (int jj = 0; jj < 2; jj++) {                                      \
                int nj = nj2*2 + jj;                                              \
                _Pragma("unroll")                                                 \
                for (int mi = 0; mi < 2; mi++) {                                  \
                    mma16816(acc[mi][nj], ah[mi][0],ah[mi][1],ah[mi][2],ah[mi][3], bh[jj], bh[jj+2]); \
                    mma16816(acc[mi][nj], ah[mi][0],ah[mi][1],ah[mi][2],ah[mi][3], bl[jj], bl[jj+2]); \
                    mma16816(acc[mi][nj], al[mi][0],al[mi][1],al[mi][2],al[mi][3], bh[jj], bh[jj+2]); \
                }                                                                 \
            }                                                                     \
        }                                                                         \
    }

__global__ void k_split(const float* __restrict__ s, __nv_bfloat16* __restrict__ h,
                        __nv_bfloat16* __restrict__ l, int n)
{
    int i = blockIdx.x * 256 + threadIdx.x;
    if (i < n) {
        float v = s[i];
        __nv_bfloat16 hb = __float2bfloat16(v);
        h[i] = hb;
        l[i] = __float2bfloat16(v - __bfloat162float(hb));
    }
}

// ---------------------------------------------------------------------------
// k_qkv_mma: D[s(128)][e(64)] = X[s][:64]·W[e][:64] + b[e]
// z=0: Q -> split [bh][s][e].  z=1/2: K/V -> transposed split [bh][e][s].
// grid (BH, 4, 3), block 256, dyn smem 55296
// ---------------------------------------------------------------------------
__global__ void __launch_bounds__(256, 2) k_qkv_mma(const float* __restrict__ bq,
                                                    const float* __restrict__ bk,
                                                    const float* __restrict__ bv)
{
    extern __shared__ uint32_t sm32[];
    int tid = threadIdx.x, wid = tid >> 5, lane = tid & 31;
    int g = lane >> 2, t4 = lane & 3;
    int m0w = (wid & 3)*32, n0w = (wid >> 2)*32;
    int bh = blockIdx.x, b = bh >> 4, h = bh & 15;
    int s0 = blockIdx.y << 7, z = blockIdx.z;

    uint32_t sb = smem_u32(sm32);
    uint32_t lrow = lane & 15, lsel = (lane >> 4) << 4;
    uint32_t aoffH = sb + (m0w + lrow)*A_STRIDE_B + lsel;
    uint32_t aoffL = aoffH + 18432;
    uint32_t boffH = sb + 36864 + (n0w + lrow)*A_STRIDE_B + lsel;
    uint32_t boffL = boffH + 9216;

    const uint4 *gA4h, *gA4l, *gB4h, *gB4l;
    const float* bias;
    if (z == 0)      { gA4h = (const uint4*)(g_Xqh + ((size_t)b*NS + s0)*NDH);
                       gA4l = (const uint4*)(g_Xql + ((size_t)b*NS + s0)*NDH);
                       gB4h = (const uint4*)(g_Wqh + h*4096);
                       gB4l = (const uint4*)(g_Wql + h*4096); bias = bq + h*64; }
    else if (z == 1) { gA4h = (const uint4*)(g_Xkh + ((size_t)b*NS + s0)*NDH);
                       gA4l = (const uint4*)(g_Xkl + ((size_t)b*NS + s0)*NDH);
                       gB4h = (const uint4*)(g_Wkh + h*4096);
                       gB4l = (const uint4*)(g_Wkl + h*4096); bias = bk + h*64; }
    else             { gA4h = (const uint4*)(g_Xvh + ((size_t)b*NS + s0)*NDH);
                       gA4l = (const uint4*)(g_Xvl + ((size_t)b*NS + s0)*NDH);
                       gB4h = (const uint4*)(g_Wvh + h*4096);
                       gB4l = (const uint4*)(g_Wvl + h*4096); bias = bv + h*64; }

    float acc[2][4][4];
#pragma unroll
    for (int mi = 0; mi < 2; mi++)
#pragma unroll
        for (int nj = 0; nj < 4; nj++)
#pragma unroll
            for (int q = 0; q < 4; q++) acc[mi][nj][q] = 0.f;

    for (int i = tid; i < 1024; i += 256) {
        int r = i >> 3, c = i & 7;
        *(uint4*)&sm32[r*36 + c*4]        = gA4h[(size_t)r*8 + c];
        *(uint4*)&sm32[4608 + r*36 + c*4] = gA4l[(size_t)r*8 + c];
    }
    for (int i = tid; i < 512; i += 256) {
        int r = i >> 3, c = i & 7;
        *(uint4*)&sm32[9216 + r*36 + c*4]  = gB4h[(size_t)r*8 + c];
        *(uint4*)&sm32[11520 + r*36 + c*4] = gB4l[(size_t)r*8 + c];
    }
    __syncthreads();
    MMA_CHUNK_LDSM();

    if (z == 0) {
        size_t base = (size_t)bh*NS*NDH;
#pragma unroll
        for (int mi = 0; mi < 2; mi++) {
            int m = m0w + mi*16 + g;
#pragma unroll
            for (int nj = 0; nj < 4; nj++) {
                int n = n0w + nj*8 + t4*2;
                float b0 = bias[n], b1 = bias[n + 1];
                uint32_t hi, lo;
                size_t i0 = base + (size_t)(s0 + m)*NDH + n;
                split2(acc[mi][nj][0] + b0, acc[mi][nj][1] + b1, hi, lo);
                *(uint32_t*)(g_Qh + i0) = hi;  *(uint32_t*)(g_Ql + i0) = lo;
                size_t i1 = base + (size_t)(s0 + m + 8)*NDH + n;
                split2(acc[mi][nj][2] + b0, acc[mi][nj][3] + b1, hi, lo);
                *(uint32_t*)(g_Qh + i1) = hi;  *(uint32_t*)(g_Ql + i1) = lo;
            }
        }
    } else {
        __syncthreads();
        float* Sg = (float*)sm32;   // [64 e][129]
#pragma unroll
        for (int mi = 0; mi < 2; mi++) {
            int m = m0w + mi*16 + g;
#pragma unroll
            for (int nj = 0; nj < 4; nj++) {
                int n = n0w + nj*8 + t4*2;
                float b0 = bias[n], b1 = bias[n + 1];
                Sg[n*129 + m]         = acc[mi][nj][0] + b0;
                Sg[(n+1)*129 + m]     = acc[mi][nj][1] + b1;
                Sg[n*129 + m + 8]     = acc[mi][nj][2] + b0;
                Sg[(n+1)*129 + m + 8] = acc[mi][nj][3] + b1;
            }
        }
        __syncthreads();
        __nv_bfloat16* dh = (z == 1 ? g_Kth : g_Vth);
        __nv_bfloat16* dl = (z == 1 ? g_Ktl : g_Vtl);
        size_t base = (size_t)bh*NDH*NS;
        for (int i = tid; i < 4096; i += 256) {
            int d = i >> 6, mm = (i & 63)*2;
            uint32_t hi, lo;
            split2(Sg[d*129 + mm], Sg[d*129 + mm + 1], hi, lo);
            size_t idx = base + (size_t)d*NS + s0 + mm;
            *(uint32_t*)(dh + idx) = hi;
            *(uint32_t*)(dl + idx) = lo;
        }
    }
}

// ---------------------------------------------------------------------------
// k_ke_mma (unchanged r6): KE split [bh][t][d]
// ---------------------------------------------------------------------------
__global__ void __launch_bounds__(256, 2) k_ke_mma(const float* __restrict__ Eb)
{
    extern __shared__ uint32_t sm32[];
    int tid = threadIdx.x, wid = tid >> 5, lane = tid & 31;
    int g = lane >> 2, t4 = lane & 3;
    int m0w = (wid & 3)*32, n0w = (wid >> 2)*32;
    int bh = blockIdx.x, t0 = blockIdx.y << 7;

    uint32_t sb = smem_u32(sm32);
    uint32_t lrow = lane & 15, lsel = (lane >> 4) << 4;
    uint32_t aoffH = sb + (m0w + lrow)*A_STRIDE_B + lsel;
    uint32_t aoffL = aoffH + 18432;
    uint32_t boffH = sb + 36864 + (n0w + lrow)*A_STRIDE_B + lsel;
    uint32_t boffL = boffH + 9216;

    float acc[2][4][4];
#pragma unroll
    for (int mi = 0; mi < 2; mi++)
#pragma unroll
        for (int nj = 0; nj < 4; nj++)
#pragma unroll
            for (int q = 0; q < 4; q++) acc[mi][nj][q] = 0.f;

    const uint4* gA4h = (const uint4*)(g_Ewh + (size_t)t0*NS);
    const uint4* gA4l = (const uint4*)(g_Ewl + (size_t)t0*NS);
    const uint4* gB4h = (const uint4*)(g_Kth + (size_t)bh*NDH*NS);
    const uint4* gB4l = (const uint4*)(g_Ktl + (size_t)bh*NDH*NS);

    for (int ch = 0; ch < 8; ch++) {
        __syncthreads();
        for (int i = tid; i < 1024; i += 256) {
            int r = i >> 3, c = i & 7;
            *(uint4*)&sm32[r*36 + c*4]        = gA4h[(size_t)r*64 + ch*8 + c];
            *(uint4*)&sm32[4608 + r*36 + c*4] = gA4l[(size_t)r*64 + ch*8 + c];
        }
        for (int i = tid; i < 512; i += 256) {
            int r = i >> 3, c = i & 7;
            *(uint4*)&sm32[9216 + r*36 + c*4]  = gB4h[(size_t)r*64 + ch*8 + c];
            *(uint4*)&sm32[11520 + r*36 + c*4] = gB4l[(size_t)r*64 + ch*8 + c];
        }
        __syncthreads();
        MMA_CHUNK_LDSM();
    }

    size_t base = (size_t)bh*NT*NDH;
#pragma unroll
    for (int mi = 0; mi < 2; mi++) {
        int m = m0w + mi*16 + g;
        float e0 = Eb[t0 + m];
        float e1 = Eb[t0 + m + 8];
#pragma unroll
        for (int nj = 0; nj < 4; nj++) {
            int n = n0w + nj*8 + t4*2;
            uint32_t hi, lo;
            size_t i0 = base + (size_t)(t0 + m)*NDH + n;
            split2(acc[mi][nj][0] + e0, acc[mi][nj][1] + e0, hi, lo);
            *(uint32_t*)(g_KEh + i0) = hi;  *(uint32_t*)(g_KEl + i0) = lo;
            size_t i1 = base + (size_t)(t0 + m + 8)*NDH + n;
            split2(acc[mi][nj][2] + e1, acc[mi][nj][3] + e1, hi, lo);
            *(uint32_t*)(g_KEh + i1) = hi;  *(uint32_t*)(g_KEl + i1) = lo;
        }
    }
}

// ---------------------------------------------------------------------------
// k_vf_mma (unchanged r6): VF^T split [bh][d][t]
// ---------------------------------------------------------------------------
__global__ void __launch_bounds__(256, 2) k_vf_mma(const float* __restrict__ Fb)
{
    extern __shared__ uint32_t sm32[];
    int tid = threadIdx.x, wid = tid >> 5, lane = tid & 31;
    int g = lane >> 2, t4 = lane & 3;
    int m0w = (wid & 3)*32, n0w = (wid >> 2)*32;
    int bh = blockIdx.x, t0 = blockIdx.y << 7;

    uint32_t sb = smem_u32(sm32);
    uint32_t lrow = lane & 15, lsel = (lane >> 4) << 4;
    uint32_t aoffH = sb + (m0w + lrow)*A_STRIDE_B + lsel;
    uint32_t aoffL = aoffH + 18432;
    uint32_t boffH = sb + 36864 + (n0w + lrow)*A_STRIDE_B + lsel;
    uint32_t boffL = boffH + 9216;

    float acc[2][4][4];
#pragma unroll
    for (int mi = 0; mi < 2; mi++)
#pragma unroll
        for (int nj = 0; nj < 4; nj++)
#pragma unroll
            for (int q = 0; q < 4; q++) acc[mi][nj][q] = 0.f;

    const uint4* gA4h = (const uint4*)(g_Fwh + (size_t)t0*NS);
    const uint4* gA4l = (const uint4*)(g_Fwl + (size_t)t0*NS);
    const uint4* gB4h = (const uint4*)(g_Vth + (size_t)bh*NDH*NS);
    const uint4* gB4l = (const uint4*)(g_Vtl + (size_t)bh*NDH*NS);

    for (int ch = 0; ch < 8; ch++) {
        __syncthreads();
        for (int i = tid; i < 1024; i += 256) {
            int r = i >> 3, c = i & 7;
            *(uint4*)&sm32[r*36 + c*4]        = gA4h[(size_t)r*64 + ch*8 + c];
            *(uint4*)&sm32[4608 + r*36 + c*4] = gA4l[(size_t)r*64 + ch*8 + c];
        }
        for (int i = tid; i < 512; i += 256) {
            int r = i >> 3, c = i & 7;
            *(uint4*)&sm32[9216 + r*36 + c*4]  = gB4h[(size_t)r*64 + ch*8 + c];
            *(uint4*)&sm32[11520 + r*36 + c*4] = gB4l[(size_t)r*64 + ch*8 + c];
        }
        __syncthreads();
        MMA_CHUNK_LDSM();
    }

    __syncthreads();
    float* Sg = (float*)sm32;
#pragma unroll
    for (int mi = 0; mi < 2; mi++) {
        int m = m0w + mi*16 + g;
        float f0 = Fb[t0 + m];
        float f1 = Fb[t0 + m + 8];
#pragma unroll
        for (int nj = 0; nj < 4; nj++) {
            int n = n0w + nj*8 + t4*2;
            Sg[n*129 + m]         = acc[mi][nj][0] + f0;
            Sg[(n+1)*129 + m]     = acc[mi][nj][1] + f0;
            Sg[n*129 + m + 8]     = acc[mi][nj][2] + f1;
            Sg[(n+1)*129 + m + 8] = acc[mi][nj][3] + f1;
        }
    }
    __syncthreads();
    size_t base = (size_t)bh*NDH*NT;
    for (int i = tid; i < 4096; i += 256) {
        int d = i >> 6, mm = (i & 63)*2;
        uint32_t hi, lo;
        split2(Sg[d*129 + mm], Sg[d*129 + mm + 1], hi, lo);
        size_t idx = base + (size_t)d*NT + t0 + mm;
        *(uint32_t*)(g_VFth + idx) = hi;
        *(uint32_t*)(g_VFtl + idx) = lo;
    }
}

// ---------------------------------------------------------------------------
// k_attn_fused: scores -> softmax -> write attn -> P·VF -> HO split.
// grid (16 s-tiles, BH), block 256, dyn smem 84992.
// Phase1 smem: KEh@0 (256x36) | KEl@9216 | Qh@18432 | Ql@19584 | redm@20736 | reds@20992
// Phase2 smem: VFh@0 (64x132) | VFl@8448   (re-uses KE region)
// Phase3 smem: Obuf@0 [8][32][65]
// ---------------------------------------------------------------------------
__global__ void __launch_bounds__(256, 1) k_attn_fused(float* __restrict__ attn_out)
{
    extern __shared__ uint32_t sm32[];
    float* sredm = (float*)(sm32 + 20736);
    float* sreds = (float*)(sm32 + 20992);
    int tid = threadIdx.x, wid = tid >> 5, lane = tid & 31;
    int g = lane >> 2, t4 = lane & 3;
    int s0 = blockIdx.x << 5, bh = blockIdx.y;

    uint32_t sb = smem_u32(sm32);
    uint32_t lrow = lane & 15, lsel = (lane >> 4) << 4;
    uint32_t aoffH = sb + 73728 + lrow*A_STRIDE_B + lsel;
    uint32_t aoffL = aoffH + 4608;
    uint32_t boffH = sb + (wid*32 + lrow)*A_STRIDE_B + lsel;
    uint32_t boffL = boffH + 36864;

    const uint4* gQ4h = (const uint4*)(g_Qh + ((size_t)bh*NS + s0)*NDH);
    const uint4* gQ4l = (const uint4*)(g_Ql + ((size_t)bh*NS + s0)*NDH);
    {
        int r = tid >> 3, c = tid & 7;
        *(uint4*)&sm32[18432 + r*36 + c*4] = gQ4h[(size_t)r*8 + c];
        *(uint4*)&sm32[19584 + r*36 + c*4] = gQ4l[(size_t)r*8 + c];
    }

    float acc[2][8][4];
#pragma unroll
    for (int mi = 0; mi < 2; mi++)
#pragma unroll
        for (int nj = 0; nj < 8; nj++)
#pragma unroll
            for (int q = 0; q < 4; q++) acc[mi][nj][q] = 0.f;

    const uint4* gKE4h = (const uint4*)(g_KEh + (size_t)bh*NT*NDH);
    const uint4* gKE4l = (const uint4*)(g_KEl + (size_t)bh*NT*NDH);

    for (int chn = 0; chn < 2; chn++) {
        if (chn) __syncthreads();
        for (int i = tid; i < 2048; i += 256) {
            int r = i >> 3, c = i & 7;
            *(uint4*)&sm32[r*36 + c*4]        = gKE4h[(size_t)(chn*256 + r)*8 + c];
            *(uint4*)&sm32[9216 + r*36 + c*4] = gKE4l[(size_t)(chn*256 + r)*8 + c];
        }
        __syncthreads();
#pragma unroll
        for (int ks = 0; ks < 4; ks++) {
            uint32_t ah[2][4], al[2][4];
#pragma unroll
            for (int mi = 0; mi < 2; mi++) {
                ldmx4(ah[mi][0],ah[mi][1],ah[mi][2],ah[mi][3], aoffH + mi*MI_STEP_B + ks*KS_STEP_B);
                ldmx4(al[mi][0],al[mi][1],al[mi][2],al[mi][3], aoffL + mi*MI_STEP_B + ks*KS_STEP_B);
            }
#pragma unroll
            for (int nj2 = 0; nj2 < 2; nj2++) {
                uint32_t bhp[4], blp[4];
                ldmx4(bhp[0],bhp[1],bhp[2],bhp[3], boffH + nj2*MI_STEP_B + ks*KS_STEP_B);
                ldmx4(blp[0],blp[1],blp[2],blp[3], boffL + nj2*MI_STEP_B + ks*KS_STEP_B);
#pragma unroll
                for (int jj = 0; jj < 2; jj++) {
                    int nj = chn*4 + nj2*2 + jj;
#pragma unroll
                    for (int mi = 0; mi < 2; mi++) {
                        mma16816(acc[mi][nj], ah[mi][0],ah[mi][1],ah[mi][2],ah[mi][3], bhp[jj], bhp[jj+2]);
                        mma16816(acc[mi][nj], ah[mi][0],ah[mi][1],ah[mi][2],ah[mi][3], blp[jj], blp[jj+2]);
                        mma16816(acc[mi][nj], al[mi][0],al[mi][1],al[mi][2],al[mi][3], bhp[jj], bhp[jj+2]);
                    }
                }
            }
        }
    }

    // ---- softmax ----
    float lm[2][2];
#pragma unroll
    for (int mi = 0; mi < 2; mi++) { lm[mi][0] = -1e30f; lm[mi][1] = -1e30f; }
#pragma unroll
    for (int mi = 0; mi < 2; mi++)
#pragma unroll
        for (int nj = 0; nj < 8; nj++) {
#pragma unroll
            for (int q = 0; q < 4; q++) acc[mi][nj][q] *= 0.125f;
            lm[mi][0] = fmaxf(lm[mi][0], fmaxf(acc[mi][nj][0], acc[mi][nj][1]));
            lm[mi][1] = fmaxf(lm[mi][1], fmaxf(acc[mi][nj][2], acc[mi][nj][3]));
        }
#pragma unroll
    for (int mi = 0; mi < 2; mi++)
#pragma unroll
        for (int hh = 0; hh < 2; hh++) {
            lm[mi][hh] = fmaxf(lm[mi][hh], __shfl_xor_sync(0xffffffffu, lm[mi][hh], 1));
            lm[mi][hh] = fmaxf(lm[mi][hh], __shfl_xor_sync(0xffffffffu, lm[mi][hh], 2));
        }
    if (t4 == 0) {
#pragma unroll
        for (int mi = 0; mi < 2; mi++) {
            sredm[wid*32 + mi*16 + g]     = lm[mi][0];
            sredm[wid*32 + mi*16 + g + 8] = lm[mi][1];
        }
    }
    __syncthreads();
    float rowm[2][2];
#pragma unroll
    for (int mi = 0; mi < 2; mi++)
#pragma unroll
        for (int hh = 0; hh < 2; hh++) {
            int row = mi*16 + g + hh*8;
            float m = sredm[row];
#pragma unroll
            for (int w = 1; w < 8; w++) m = fmaxf(m, sredm[w*32 + row]);
            rowm[mi][hh] = m;
        }
    float ls[2][2] = {{0.f,0.f},{0.f,0.f}};
#pragma unroll
    for (int mi = 0; mi < 2; mi++)
#pragma unroll
        for (int nj = 0; nj < 8; nj++) {
            acc[mi][nj][0] = __expf(acc[mi][nj][0] - rowm[mi][0]);
            acc[mi][nj][1] = __expf(acc[mi][nj][1] - rowm[mi][0]);
            acc[mi][nj][2] = __expf(acc[mi][nj][2] - rowm[mi][1]);
            acc[mi][nj][3] = __expf(acc[mi][nj][3] - rowm[mi][1]);
            ls[mi][0] += acc[mi][nj][0] + acc[mi][nj][1];
            ls[mi][1] += acc[mi][nj][2] + acc[mi][nj][3];
        }
#pragma unroll
    for (int mi = 0; mi < 2; mi++)
#pragma unroll
        for (int hh = 0; hh < 2; hh++) {
            ls[mi][hh] += __shfl_xor_sync(0xffffffffu, ls[mi][hh], 1);
            ls[mi][hh] += __shfl_xor_sync(0xffffffffu, ls[mi][hh], 2);
        }
    if (t4 == 0) {
#pragma unroll
        for (int mi = 0; mi < 2; mi++) {
            sreds[wid*32 + mi*16 + g]     = ls[mi][0];
            sreds[wid*32 + mi*16 + g + 8] = ls[mi][1];
        }
    }
    __syncthreads();
    float inv[2][2];
#pragma unroll
    for (int mi = 0; mi < 2; mi++)
#pragma unroll
        for (int hh = 0; hh < 2; hh++) {
            int row = mi*16 + g + hh*8;
            float s = 0.f;
#pragma unroll
            for (int w = 0; w < 8; w++) s += sreds[w*32 + row];
            inv[mi][hh] = 1.f / s;
        }

    // normalize P in-place, write attn
#pragma unroll
    for (int mi = 0; mi < 2; mi++) {
        size_t r0 = ((size_t)bh*NS + s0 + mi*16 + g)*NT;
        size_t r1 = r0 + 8*NT;
#pragma unroll
        for (int nj = 0; nj < 8; nj++) {
            acc[mi][nj][0] *= inv[mi][0];  acc[mi][nj][1] *= inv[mi][0];
            acc[mi][nj][2] *= inv[mi][1];  acc[mi][nj][3] *= inv[mi][1];
            int col = (nj >> 2)*256 + wid*32 + (nj & 3)*8 + 2*t4;
            *(float2*)(attn_out + r0 + col) = make_float2(acc[mi][nj][0], acc[mi][nj][1]);
            *(float2*)(attn_out + r1 + col) = make_float2(acc[mi][nj][2], acc[mi][nj][3]);
        }
    }

    // ---- P·VF (each warp: its own 64 t-cols, all 64 d) ----
    float acc_o[2][8][4];
#pragma unroll
    for (int mi = 0; mi < 2; mi++)
#pragma unroll
        for (int nd = 0; nd < 8; nd++)
#pragma unroll
            for (int q = 0; q < 4; q++) acc_o[mi][nd][q] = 0.f;

    const uint4* gVF4h = (const uint4*)(g_VFth + (size_t)bh*NDH*NT);
    const uint4* gVF4l = (const uint4*)(g_VFtl + (size_t)bh*NDH*NT);
    uint32_t b_pvH = sb + lrow*528 + wid*64 + lsel;
    uint32_t b_pvL = b_pvH + 33792;

    for (int hf = 0; hf < 2; hf++) {
        __syncthreads();   // prior phase's smem reads complete
        for (int i = tid; i < 2048; i += 256) {
            int r = i >> 5, c = i & 31;
            *(uint4*)&sm32[r*132 + c*4]        = gVF4h[(size_t)r*64 + hf*32 + c];
            *(uint4*)&sm32[8448 + r*132 + c*4] = gVF4l[(size_t)r*64 + hf*32 + c];
        }
        __syncthreads();
        // P fragments for this half
        uint32_t pah[2][2][4], pal[2][2][4];   // [ks2][mi][4]
#pragma unroll
        for (int ks2 = 0; ks2 < 2; ks2++)
#pragma unroll
            for (int mi = 0; mi < 2; mi++) {
                int nj0 = hf*4 + ks2*2, nj1 = nj0 + 1;
                split2(acc[mi][nj0][0], acc[mi][nj0][1], pah[ks2][mi][0], pal[ks2][mi][0]);
                split2(acc[mi][nj0][2], acc[mi][nj0][3], pah[ks2][mi][1], pal[ks2][mi][1]);
                split2(acc[mi][nj1][0], acc[mi][nj1][1], pah[ks2][mi][2], pal[ks2][mi][2]);
                split2(acc[mi][nj1][2], acc[mi][nj1][3], pah[ks2][mi][3], pal[ks2][mi][3]);
            }
#pragma unroll
        for (int dt = 0; dt < 4; dt++) {
#pragma unroll
            for (int ks2 = 0; ks2 < 2; ks2++) {
                uint32_t bhv[4], blv[4];
                ldmx4(bhv[0],bhv[1],bhv[2],bhv[3], b_pvH + dt*8448 + ks2*32);
                ldmx4(blv[0],blv[1],blv[2],blv[3], b_pvL + dt*8448 + ks2*32);
#pragma unroll
                for (int jj = 0; jj < 2; jj++) {
                    int nd = dt*2 + jj;
#pragma unroll
                    for (int mi = 0; mi < 2; mi++) {
                        mma16816(acc_o[mi][nd], pah[ks2][mi][0],pah[ks2][mi][1],pah[ks2][mi][2],pah[ks2][mi][3], bhv[jj], bhv[jj+2]);
                        mma16816(acc_o[mi][nd], pah[ks2][mi][0],pah[ks2][mi][1],pah[ks2][mi][2],pah[ks2][mi][3], blv[jj], blv[jj+2]);
                        mma16816(acc_o[mi][nd], pal[ks2][mi][0],pal[ks2][mi][1],pal[ks2][mi][2],pal[ks2][mi][3], bhv[jj], bhv[jj+2]);
                    }
                }
            }
        }
    }

    // ---- cross-warp reduction ----
    __syncthreads();
    float* Ob = (float*)sm32;   // [8][32][65]
#pragma unroll
    for (int mi = 0; mi < 2; mi++)
#pragma unroll
        for (int nd = 0; nd < 8; nd++) {
            int m = mi*16 + g, n = nd*8 + 2*t4;
            Ob[wid*2080 + m*65 + n]       = acc_o[mi][nd][0];
            Ob[wid*2080 + m*65 + n + 1]   = acc_o[mi][nd][1];
            Ob[wid*2080 + (m+8)*65 + n]   = acc_o[mi][nd][2];
            Ob[wid*2080 + (m+8)*65 + n+1] = acc_o[mi][nd][3];
        }
    __syncthreads();
    {
        int s = tid >> 3, dg = (tid & 7)*8;
        float o[8];
#pragma unroll
        for (int j = 0; j < 8; j++) o[j] = 0.f;
#pragma unroll
        for (int w = 0; w < 8; w++)
#pragma unroll
            for (int j = 0; j < 8; j++) o[j] += Ob[w*2080 + s*65 + dg + j];
        size_t base = ((size_t)bh*NS + s0 + s)*NDH + dg;
#pragma unroll
        for (int j = 0; j < 8; j += 2) {
            uint32_t hi, lo;
            split2(o[j], o[j+1], hi, lo);
            *(uint32_t*)(g_HOh + base + j) = hi;
            *(uint32_t*)(g_HOl + base + j) = lo;
        }
    }
}

// ---------------------------------------------------------------------------
// k_out_mma (unchanged r6)
// ---------------------------------------------------------------------------
__global__ void __launch_bounds__(256, 2) k_out_mma(const float* __restrict__ Ob,
                                                    float* __restrict__ out)
{
    extern __shared__ uint32_t sm32[];
    int tid = threadIdx.x, wid = tid >> 5, lane = tid & 31;
    int g = lane >> 2, t4 = lane & 3;
    int m0w = (wid & 3)*32, n0w = (wid >> 2)*32;
    int m0 = blockIdx.x << 7;
    int b  = blockIdx.x >> 2;
    int sbase = (blockIdx.x & 3) << 7;
    int n0 = blockIdx.y << 6;

    uint32_t sb = smem_u32(sm32);
    uint32_t lrow = lane & 15, lsel = (lane >> 4) << 4;
    uint32_t aoffH = sb + (m0w + lrow)*A_STRIDE_B + lsel;
    uint32_t aoffL = aoffH + 18432;
    uint32_t boffH = sb + 36864 + (n0w + lrow)*A_STRIDE_B + lsel;
    uint32_t boffL = boffH + 9216;

    float acc[2][4][4];
#pragma unroll
    for (int mi = 0; mi < 2; mi++)
#pragma unroll
        for (int nj = 0; nj < 4; nj++)
#pragma unroll
            for (int q = 0; q < 4; q++) acc[mi][nj][q] = 0.f;

    for (int kc = 0; kc < 16; kc++) {
        const uint4* gA4h = (const uint4*)(g_HOh + ((size_t)(b*NH + kc)*NS + sbase)*NDH);
        const uint4* gA4l = (const uint4*)(g_HOl + ((size_t)(b*NH + kc)*NS + sbase)*NDH);
        const uint4* gB4h = (const uint4*)(g_Owh + (size_t)n0*NDM);
        const uint4* gB4l = (const uint4*)(g_Owl + (size_t)n0*NDM);
        __syncthreads();
        for (int i = tid; i < 1024; i += 256) {
            int r = i >> 3, c = i & 7;
            *(uint4*)&sm32[r*36 + c*4]        = gA4h[(size_t)r*8 + c];
            *(uint4*)&sm32[4608 + r*36 + c*4] = gA4l[(size_t)r*8 + c];
        }
        for (int i = tid; i < 512; i += 256) {
            int r = i >> 3, c = i & 7;
            *(uint4*)&sm32[9216 + r*36 + c*4]  = gB4h[(size_t)r*128 + kc*8 + c];
            *(uint4*)&sm32[11520 + r*36 + c*4] = gB4l[(size_t)r*128 + kc*8 + c];
        }
        __syncthreads();
        MMA_CHUNK_LDSM();
    }

    __syncthreads();
    float* Sg = (float*)sm32;
#pragma unroll
    for (int mi = 0; mi < 2; mi++) {
        int m = m0w + mi*16 + g;
#pragma unroll
        for (int nj = 0; nj < 4; nj++) {
            int n = n0w + nj*8 + t4*2;
            float o0 = Ob[n0 + n];
            float o1 = Ob[n0 + n + 1];
            Sg[m*65 + n]         = acc[mi][nj][0] + o0;
            Sg[m*65 + n + 1]     = acc[mi][nj][1] + o1;
            Sg[(m+8)*65 + n]     = acc[mi][nj][2] + o0;
            Sg[(m+8)*65 + n + 1] = acc[mi][nj][3] + o1;
        }
    }
    __syncthreads();
    for (int i = tid; i < 8192; i += 256) {
        int r = i >> 6, c = i & 63;
        out[(size_t)(m0 + r)*NDM + n0 + c] = Sg[r*65 + c];
    }
}

// ---------------------------------------------------------------------------
extern "C" void kernel_launch(void* const* d_in, const int* in_sizes, int n_in,
                              void* d_out, int out_size)
{
    const float* query = (const float*)d_in[0];
    const float* key   = (const float*)d_in[1];
    const float* value = (const float*)d_in[2];
    const float* bq    = (const float*)d_in[4];
    const float* bk    = (const float*)d_in[6];
    const float* bv    = (const float*)d_in[8];
    const float* Wq    = (const float*)d_in[3];
    const float* Wk    = (const float*)d_in[5];
    const float* Wv    = (const float*)d_in[7];
    const float* E_w   = (const float*)d_in[9];
    const float* E_b   = (const float*)d_in[10];
    const float* F_w   = (const float*)d_in[11];
    const float* F_b   = (const float*)d_in[12];
    const float* out_w = (const float*)d_in[13];
    const float* out_b = (const float*)d_in[14];

    const long long mha_elems  = (long long)NB*NS*NDM;
    const long long attn_elems = (long long)BH*NS*NT;

    float* outp = (float*)d_out;
    float* mha_ptr;
    float* attn_ptr;
    if ((long long)out_size >= mha_elems + attn_elems) {
        mha_ptr  = outp;
        attn_ptr = outp + mha_elems;
    } else if ((long long)out_size == attn_elems) {
        attn_ptr = outp;
        cudaGetSymbolAddress((void**)&mha_ptr, g_MHA_FB);
    } else {
        mha_ptr = outp;
        cudaGetSymbolAddress((void**)&attn_ptr, g_ATTN_FB);
    }

    __nv_bfloat16 *p[18];
    cudaGetSymbolAddress((void**)&p[0],  g_Ewh); cudaGetSymbolAddress((void**)&p[1],  g_Ewl);
    cudaGetSymbolAddress((void**)&p[2],  g_Fwh); cudaGetSymbolAddress((void**)&p[3],  g_Fwl);
    cudaGetSymbolAddress((void**)&p[4],  g_Owh); cudaGetSymbolAddress((void**)&p[5],  g_Owl);
    cudaGetSymbolAddress((void**)&p[6],  g_Xqh); cudaGetSymbolAddress((void**)&p[7],  g_Xql);
    cudaGetSymbolAddress((void**)&p[8],  g_Xkh); cudaGetSymbolAddress((void**)&p[9],  g_Xkl);
    cudaGetSymbolAddress((void**)&p[10], g_Xvh); cudaGetSymbolAddress((void**)&p[11], g_Xvl);
    cudaGetSymbolAddress((void**)&p[12], g_Wqh); cudaGetSymbolAddress((void**)&p[13], g_Wql);
    cudaGetSymbolAddress((void**)&p[14], g_Wkh); cudaGetSymbolAddress((void**)&p[15], g_Wkl);
    cudaGetSymbolAddress((void**)&p[16], g_Wvh); cudaGetSymbolAddress((void**)&p[17], g_Wvl);

    cudaFuncSetAttribute(k_qkv_mma,  cudaFuncAttributeMaxDynamicSharedMemorySize, 55296);
    cudaFuncSetAttribute(k_ke_mma,   cudaFuncAttributeMaxDynamicSharedMemorySize, 55296);
    cudaFuncSetAttribute(k_vf_mma,   cudaFuncAttributeMaxDynamicSharedMemorySize, 55296);
    cudaFuncSetAttribute(k_out_mma,  cudaFuncAttributeMaxDynamicSharedMemorySize, 55296);
    cudaFuncSetAttribute(k_attn_fused, cudaFuncAttributeMaxDynamicSharedMemorySize, 84992);

    const int NX = NB*NS*NDH;       // 1,048,576
    const int NW = NH*NDH*NDH;      // 65,536
    k_split<<<(NT*NS + 255)/256, 256>>>(E_w, p[0], p[1], NT*NS);
    k_split<<<(NT*NS + 255)/256, 256>>>(F_w, p[2], p[3], NT*NS);
    k_split<<<(NDM*NDM + 255)/256, 256>>>(out_w, p[4], p[5], NDM*NDM);
    k_split<<<(NX + 255)/256, 256>>>(query, p[6],  p[7],  NX);
    k_split<<<(NX + 255)/256, 256>>>(key,   p[8],  p[9],  NX);
    k_split<<<(NX + 255)/256, 256>>>(value, p[10], p[11], NX);
    k_split<<<(NW + 255)/256, 256>>>(Wq, p[12], p[13], NW);
    k_split<<<(NW + 255)/256, 256>>>(Wk, p[14], p[15], NW);
    k_split<<<(NW + 255)/256, 256>>>(Wv, p[16], p[17], NW);

    k_qkv_mma<<<dim3(BH, 4, 3), 256, 55296>>>(bq, bk, bv);
    k_ke_mma<<<dim3(BH, 4), 256, 55296>>>(E_b);
    k_vf_mma<<<dim3(BH, 4), 256, 55296>>>(F_b);
    k_attn_fused<<<dim3(16, BH), 256, 84992>>>(attn_ptr);
    k_out_mma<<<dim3((NB*NS)/128, NDM/64), 256, 55296>>>(out_b, mha_ptr);
}

// round 8
// speedup vs baseline: 2.0520x; 1.1199x over previous
#include <cuda_runtime.h>
#include <cuda_bf16.h>
#include <cstdint>

#define NB 32
#define NS 512
#define NH 16
#define NDH 64
#define NDM 1024
#define NT 512
#define BH (NB*NH)

// ---------------- global scratch ----------------
__device__ __nv_bfloat16 g_Xqh[NB*NS*NDH], g_Xql[NB*NS*NDH];
__device__ __nv_bfloat16 g_Xkh[NB*NS*NDH], g_Xkl[NB*NS*NDH];
__device__ __nv_bfloat16 g_Xvh[NB*NS*NDH], g_Xvl[NB*NS*NDH];
__device__ __nv_bfloat16 g_Wqh[NH*NDH*NDH], g_Wql[NH*NDH*NDH];
__device__ __nv_bfloat16 g_Wkh[NH*NDH*NDH], g_Wkl[NH*NDH*NDH];
__device__ __nv_bfloat16 g_Wvh[NH*NDH*NDH], g_Wvl[NH*NDH*NDH];
__device__ __nv_bfloat16 g_Qh [(size_t)BH*NS*NDH];
__device__ __nv_bfloat16 g_Ql [(size_t)BH*NS*NDH];
__device__ __nv_bfloat16 g_Kth[(size_t)BH*NDH*NS];
__device__ __nv_bfloat16 g_Ktl[(size_t)BH*NDH*NS];
__device__ __nv_bfloat16 g_Vth[(size_t)BH*NDH*NS];
__device__ __nv_bfloat16 g_Vtl[(size_t)BH*NDH*NS];
__device__ __nv_bfloat16 g_KEh[(size_t)BH*NT*NDH];
__device__ __nv_bfloat16 g_KEl[(size_t)BH*NT*NDH];
__device__ __nv_bfloat16 g_VFth[(size_t)BH*NDH*NT];
__device__ __nv_bfloat16 g_VFtl[(size_t)BH*NDH*NT];
__device__ __nv_bfloat16 g_Ewh[NT*NS], g_Ewl[NT*NS];
__device__ __nv_bfloat16 g_Fwh[NT*NS], g_Fwl[NT*NS];
__device__ __nv_bfloat16 g_Owh[NDM*NDM], g_Owl[NDM*NDM];
__device__ __nv_bfloat16 g_HOh[(size_t)BH*NS*NDH];
__device__ __nv_bfloat16 g_HOl[(size_t)BH*NS*NDH];
__device__ float g_ATTN_FB[(size_t)BH*NS*NT];
__device__ float g_MHA_FB [(size_t)NB*NS*NDM];

// ---------------- helpers ----------------
__device__ __forceinline__ uint32_t smem_u32(const void* p) {
    uint32_t a;
    asm("{ .reg .u64 t; cvta.to.shared.u64 t, %1; cvt.u32.u64 %0, t; }" : "=r"(a) : "l"(p));
    return a;
}
__device__ __forceinline__ void mma16816(float c[4],
                                         uint32_t a0, uint32_t a1, uint32_t a2, uint32_t a3,
                                         uint32_t b0, uint32_t b1)
{
    asm volatile(
        "mma.sync.aligned.m16n8k16.row.col.f32.bf16.bf16.f32 "
        "{%0,%1,%2,%3}, {%4,%5,%6,%7}, {%8,%9}, {%0,%1,%2,%3};"
        : "+f"(c[0]), "+f"(c[1]), "+f"(c[2]), "+f"(c[3])
        : "r"(a0), "r"(a1), "r"(a2), "r"(a3), "r"(b0), "r"(b1));
}
__device__ __forceinline__ void ldmx4(uint32_t& r0, uint32_t& r1, uint32_t& r2, uint32_t& r3,
                                      uint32_t addr)
{
    asm volatile("ldmatrix.sync.aligned.m8n8.x4.shared.b16 {%0,%1,%2,%3}, [%4];"
                 : "=r"(r0), "=r"(r1), "=r"(r2), "=r"(r3) : "r"(addr));
}
__device__ __forceinline__ void split2(float x, float y, uint32_t& hi, uint32_t& lo)
{
    __nv_bfloat162 h = __floats2bfloat162_rn(x, y);
    float hx = __bfloat162float(h.x), hy = __bfloat162float(h.y);
    __nv_bfloat162 l = __floats2bfloat162_rn(x - hx, y - hy);
    hi = *(uint32_t*)&h;
    lo = *(uint32_t*)&l;
}
__device__ __forceinline__ void split_store(float v, __nv_bfloat16* h, __nv_bfloat16* l, int i)
{
    __nv_bfloat16 hb = __float2bfloat16(v);
    h[i] = hb;
    l[i] = __float2bfloat16(v - __bfloat162float(hb));
}

// smem geometry (u32 units): row stride 36 words (144B)
#define A_STRIDE_B 144
#define MI_STEP_B  2304
#define KS_STEP_B  32

#define MMA_CHUNK_LDSM()                                                          \
    _Pragma("unroll")                                                             \
    for (int ks = 0; ks < 4; ks++) {                                              \
        uint32_t ah[2][4], al[2][4];                                              \
        _Pragma("unroll")                                                         \
        for (int mi = 0; mi < 2; mi++) {                                          \
            ldmx4(ah[mi][0],ah[mi][1],ah[mi][2],ah[mi][3], aoffH + mi*MI_STEP_B + ks*KS_STEP_B); \
            ldmx4(al[mi][0],al[mi][1],al[mi][2],al[mi][3], aoffL + mi*MI_STEP_B + ks*KS_STEP_B); \
        }                                                                         \
        _Pragma("unroll")                                                         \
        for (int nj2 = 0; nj2 < 2; nj2++) {                                       \
            uint32_t bh[4], bl[4];                                                \
            ldmx4(bh[0],bh[1],bh[2],bh[3], boffH + nj2*MI_STEP_B + ks*KS_STEP_B); \
            ldmx4(bl[0],bl[1],bl[2],bl[3], boffL + nj2*MI_STEP_B + ks*KS_STEP_B); \
            _Pragma("unroll")                                                     \
            for (int jj = 0; jj < 2; jj++) {                                      \
                int nj = nj2*2 + jj;                                              \
                _Pragma("unroll")                                                 \
                for (int mi = 0; mi < 2; mi++) {                                  \
                    mma16816(acc[mi][nj], ah[mi][0],ah[mi][1],ah[mi][2],ah[mi][3], bh[jj], bh[jj+2]); \
                    mma16816(acc[mi][nj], ah[mi][0],ah[mi][1],ah[mi][2],ah[mi][3], bl[jj], bl[jj+2]); \
                    mma16816(acc[mi][nj], al[mi][0],al[mi][1],al[mi][2],al[mi][3], bh[jj], bh[jj+2]); \
                }                                                                 \
            }                                                                     \
        }                                                                         \
    }

// ---------------------------------------------------------------------------
// combined split kernels (2 launches instead of 9 -> ncu slot alignment)
// ---------------------------------------------------------------------------
#define NX (NB*NS*NDH)    // 1,048,576
#define NW (NH*NDH*NDH)   // 65,536
__global__ void k_split6(const float* __restrict__ xq, const float* __restrict__ xk,
                         const float* __restrict__ xv, const float* __restrict__ wq,
                         const float* __restrict__ wk, const float* __restrict__ wv)
{
    int i = blockIdx.x*256 + threadIdx.x;
    if (i < NX)                  split_store(xq[i], g_Xqh, g_Xql, i);
    else if (i < 2*NX)           split_store(xk[i - NX], g_Xkh, g_Xkl, i - NX);
    else if (i < 3*NX)           split_store(xv[i - 2*NX], g_Xvh, g_Xvl, i - 2*NX);
    else if (i < 3*NX + NW)      split_store(wq[i - 3*NX], g_Wqh, g_Wql, i - 3*NX);
    else if (i < 3*NX + 2*NW)    split_store(wk[i - 3*NX - NW], g_Wkh, g_Wkl, i - 3*NX - NW);
    else if (i < 3*NX + 3*NW)    split_store(wv[i - 3*NX - 2*NW], g_Wvh, g_Wvl, i - 3*NX - 2*NW);
}
__global__ void k_split3(const float* __restrict__ ew, const float* __restrict__ fw,
                         const float* __restrict__ ow)
{
    const int NE = NT*NS;
    int i = blockIdx.x*256 + threadIdx.x;
    if (i < NE)                  split_store(ew[i], g_Ewh, g_Ewl, i);
    else if (i < 2*NE)           split_store(fw[i - NE], g_Fwh, g_Fwl, i - NE);
    else if (i < 2*NE + NDM*NDM) split_store(ow[i - 2*NE], g_Owh, g_Owl, i - 2*NE);
}

// ---------------------------------------------------------------------------
// k_qkv_mma (unchanged r7)
// ---------------------------------------------------------------------------
__global__ void __launch_bounds__(256, 2) k_qkv_mma(const float* __restrict__ bq,
                                                    const float* __restrict__ bk,
                                                    const float* __restrict__ bv)
{
    extern __shared__ uint32_t sm32[];
    int tid = threadIdx.x, wid = tid >> 5, lane = tid & 31;
    int g = lane >> 2, t4 = lane & 3;
    int m0w = (wid & 3)*32, n0w = (wid >> 2)*32;
    int bh = blockIdx.x, b = bh >> 4, h = bh & 15;
    int s0 = blockIdx.y << 7, z = blockIdx.z;

    uint32_t sb = smem_u32(sm32);
    uint32_t lrow = lane & 15, lsel = (lane >> 4) << 4;
    uint32_t aoffH = sb + (m0w + lrow)*A_STRIDE_B + lsel;
    uint32_t aoffL = aoffH + 18432;
    uint32_t boffH = sb + 36864 + (n0w + lrow)*A_STRIDE_B + lsel;
    uint32_t boffL = boffH + 9216;

    const uint4 *gA4h, *gA4l, *gB4h, *gB4l;
    const float* bias;
    if (z == 0)      { gA4h = (const uint4*)(g_Xqh + ((size_t)b*NS + s0)*NDH);
                       gA4l = (const uint4*)(g_Xql + ((size_t)b*NS + s0)*NDH);
                       gB4h = (const uint4*)(g_Wqh + h*4096);
                       gB4l = (const uint4*)(g_Wql + h*4096); bias = bq + h*64; }
    else if (z == 1) { gA4h = (const uint4*)(g_Xkh + ((size_t)b*NS + s0)*NDH);
                       gA4l = (const uint4*)(g_Xkl + ((size_t)b*NS + s0)*NDH);
                       gB4h = (const uint4*)(g_Wkh + h*4096);
                       gB4l = (const uint4*)(g_Wkl + h*4096); bias = bk + h*64; }
    else             { gA4h = (const uint4*)(g_Xvh + ((size_t)b*NS + s0)*NDH);
                       gA4l = (const uint4*)(g_Xvl + ((size_t)b*NS + s0)*NDH);
                       gB4h = (const uint4*)(g_Wvh + h*4096);
                       gB4l = (const uint4*)(g_Wvl + h*4096); bias = bv + h*64; }

    float acc[2][4][4];
#pragma unroll
    for (int mi = 0; mi < 2; mi++)
#pragma unroll
        for (int nj = 0; nj < 4; nj++)
#pragma unroll
            for (int q = 0; q < 4; q++) acc[mi][nj][q] = 0.f;

    for (int i = tid; i < 1024; i += 256) {
        int r = i >> 3, c = i & 7;
        *(uint4*)&sm32[r*36 + c*4]        = gA4h[(size_t)r*8 + c];
        *(uint4*)&sm32[4608 + r*36 + c*4] = gA4l[(size_t)r*8 + c];
    }
    for (int i = tid; i < 512; i += 256) {
        int r = i >> 3, c = i & 7;
        *(uint4*)&sm32[9216 + r*36 + c*4]  = gB4h[(size_t)r*8 + c];
        *(uint4*)&sm32[11520 + r*36 + c*4] = gB4l[(size_t)r*8 + c];
    }
    __syncthreads();
    MMA_CHUNK_LDSM();

    if (z == 0) {
        size_t base = (size_t)bh*NS*NDH;
#pragma unroll
        for (int mi = 0; mi < 2; mi++) {
            int m = m0w + mi*16 + g;
#pragma unroll
            for (int nj = 0; nj < 4; nj++) {
                int n = n0w + nj*8 + t4*2;
                float b0 = bias[n], b1 = bias[n + 1];
                uint32_t hi, lo;
                size_t i0 = base + (size_t)(s0 + m)*NDH + n;
                split2(acc[mi][nj][0] + b0, acc[mi][nj][1] + b1, hi, lo);
                *(uint32_t*)(g_Qh + i0) = hi;  *(uint32_t*)(g_Ql + i0) = lo;
                size_t i1 = base + (size_t)(s0 + m + 8)*NDH + n;
                split2(acc[mi][nj][2] + b0, acc[mi][nj][3] + b1, hi, lo);
                *(uint32_t*)(g_Qh + i1) = hi;  *(uint32_t*)(g_Ql + i1) = lo;
            }
        }
    } else {
        __syncthreads();
        float* Sg = (float*)sm32;
#pragma unroll
        for (int mi = 0; mi < 2; mi++) {
            int m = m0w + mi*16 + g;
#pragma unroll
            for (int nj = 0; nj < 4; nj++) {
                int n = n0w + nj*8 + t4*2;
                float b0 = bias[n], b1 = bias[n + 1];
                Sg[n*129 + m]         = acc[mi][nj][0] + b0;
                Sg[(n+1)*129 + m]     = acc[mi][nj][1] + b1;
                Sg[n*129 + m + 8]     = acc[mi][nj][2] + b0;
                Sg[(n+1)*129 + m + 8] = acc[mi][nj][3] + b1;
            }
        }
        __syncthreads();
        __nv_bfloat16* dh = (z == 1 ? g_Kth : g_Vth);
        __nv_bfloat16* dl = (z == 1 ? g_Ktl : g_Vtl);
        size_t base = (size_t)bh*NDH*NS;
        for (int i = tid; i < 4096; i += 256) {
            int d = i >> 6, mm = (i & 63)*2;
            uint32_t hi, lo;
            split2(Sg[d*129 + mm], Sg[d*129 + mm + 1], hi, lo);
            size_t idx = base + (size_t)d*NS + s0 + mm;
            *(uint32_t*)(dh + idx) = hi;
            *(uint32_t*)(dl + idx) = lo;
        }
    }
}

// ---------------------------------------------------------------------------
// k_ke_mma (unchanged)
// ---------------------------------------------------------------------------
__global__ void __launch_bounds__(256, 2) k_ke_mma(const float* __restrict__ Eb)
{
    extern __shared__ uint32_t sm32[];
    int tid = threadIdx.x, wid = tid >> 5, lane = tid & 31;
    int g = lane >> 2, t4 = lane & 3;
    int m0w = (wid & 3)*32, n0w = (wid >> 2)*32;
    int bh = blockIdx.x, t0 = blockIdx.y << 7;

    uint32_t sb = smem_u32(sm32);
    uint32_t lrow = lane & 15, lsel = (lane >> 4) << 4;
    uint32_t aoffH = sb + (m0w + lrow)*A_STRIDE_B + lsel;
    uint32_t aoffL = aoffH + 18432;
    uint32_t boffH = sb + 36864 + (n0w + lrow)*A_STRIDE_B + lsel;
    uint32_t boffL = boffH + 9216;

    float acc[2][4][4];
#pragma unroll
    for (int mi = 0; mi < 2; mi++)
#pragma unroll
        for (int nj = 0; nj < 4; nj++)
#pragma unroll
            for (int q = 0; q < 4; q++) acc[mi][nj][q] = 0.f;

    const uint4* gA4h = (const uint4*)(g_Ewh + (size_t)t0*NS);
    const uint4* gA4l = (const uint4*)(g_Ewl + (size_t)t0*NS);
    const uint4* gB4h = (const uint4*)(g_Kth + (size_t)bh*NDH*NS);
    const uint4* gB4l = (const uint4*)(g_Ktl + (size_t)bh*NDH*NS);

    for (int ch = 0; ch < 8; ch++) {
        __syncthreads();
        for (int i = tid; i < 1024; i += 256) {
            int r = i >> 3, c = i & 7;
            *(uint4*)&sm32[r*36 + c*4]        = gA4h[(size_t)r*64 + ch*8 + c];
            *(uint4*)&sm32[4608 + r*36 + c*4] = gA4l[(size_t)r*64 + ch*8 + c];
        }
        for (int i = tid; i < 512; i += 256) {
            int r = i >> 3, c = i & 7;
            *(uint4*)&sm32[9216 + r*36 + c*4]  = gB4h[(size_t)r*64 + ch*8 + c];
            *(uint4*)&sm32[11520 + r*36 + c*4] = gB4l[(size_t)r*64 + ch*8 + c];
        }
        __syncthreads();
        MMA_CHUNK_LDSM();
    }

    size_t base = (size_t)bh*NT*NDH;
#pragma unroll
    for (int mi = 0; mi < 2; mi++) {
        int m = m0w + mi*16 + g;
        float e0 = Eb[t0 + m];
        float e1 = Eb[t0 + m + 8];
#pragma unroll
        for (int nj = 0; nj < 4; nj++) {
            int n = n0w + nj*8 + t4*2;
            uint32_t hi, lo;
            size_t i0 = base + (size_t)(t0 + m)*NDH + n;
            split2(acc[mi][nj][0] + e0, acc[mi][nj][1] + e0, hi, lo);
            *(uint32_t*)(g_KEh + i0) = hi;  *(uint32_t*)(g_KEl + i0) = lo;
            size_t i1 = base + (size_t)(t0 + m + 8)*NDH + n;
            split2(acc[mi][nj][2] + e1, acc[mi][nj][3] + e1, hi, lo);
            *(uint32_t*)(g_KEh + i1) = hi;  *(uint32_t*)(g_KEl + i1) = lo;
        }
    }
}

// ---------------------------------------------------------------------------
// k_vf_mma (unchanged)
// ---------------------------------------------------------------------------
__global__ void __launch_bounds__(256, 2) k_vf_mma(const float* __restrict__ Fb)
{
    extern __shared__ uint32_t sm32[];
    int tid = threadIdx.x, wid = tid >> 5, lane = tid & 31;
    int g = lane >> 2, t4 = lane & 3;
    int m0w = (wid & 3)*32, n0w = (wid >> 2)*32;
    int bh = blockIdx.x, t0 = blockIdx.y << 7;

    uint32_t sb = smem_u32(sm32);
    uint32_t lrow = lane & 15, lsel = (lane >> 4) << 4;
    uint32_t aoffH = sb + (m0w + lrow)*A_STRIDE_B + lsel;
    uint32_t aoffL = aoffH + 18432;
    uint32_t boffH = sb + 36864 + (n0w + lrow)*A_STRIDE_B + lsel;
    uint32_t boffL = boffH + 9216;

    float acc[2][4][4];
#pragma unroll
    for (int mi = 0; mi < 2; mi++)
#pragma unroll
        for (int nj = 0; nj < 4; nj++)
#pragma unroll
            for (int q = 0; q < 4; q++) acc[mi][nj][q] = 0.f;

    const uint4* gA4h = (const uint4*)(g_Fwh + (size_t)t0*NS);
    const uint4* gA4l = (const uint4*)(g_Fwl + (size_t)t0*NS);
    const uint4* gB4h = (const uint4*)(g_Vth + (size_t)bh*NDH*NS);
    const uint4* gB4l = (const uint4*)(g_Vtl + (size_t)bh*NDH*NS);

    for (int ch = 0; ch < 8; ch++) {
        __syncthreads();
        for (int i = tid; i < 1024; i += 256) {
            int r = i >> 3, c = i & 7;
            *(uint4*)&sm32[r*36 + c*4]        = gA4h[(size_t)r*64 + ch*8 + c];
            *(uint4*)&sm32[4608 + r*36 + c*4] = gA4l[(size_t)r*64 + ch*8 + c];
        }
        for (int i = tid; i < 512; i += 256) {
            int r = i >> 3, c = i & 7;
            *(uint4*)&sm32[9216 + r*36 + c*4]  = gB4h[(size_t)r*64 + ch*8 + c];
            *(uint4*)&sm32[11520 + r*36 + c*4] = gB4l[(size_t)r*64 + ch*8 + c];
        }
        __syncthreads();
        MMA_CHUNK_LDSM();
    }

    __syncthreads();
    float* Sg = (float*)sm32;
#pragma unroll
    for (int mi = 0; mi < 2; mi++) {
        int m = m0w + mi*16 + g;
        float f0 = Fb[t0 + m];
        float f1 = Fb[t0 + m + 8];
#pragma unroll
        for (int nj = 0; nj < 4; nj++) {
            int n = n0w + nj*8 + t4*2;
            Sg[n*129 + m]         = acc[mi][nj][0] + f0;
            Sg[(n+1)*129 + m]     = acc[mi][nj][1] + f0;
            Sg[n*129 + m + 8]     = acc[mi][nj][2] + f1;
            Sg[(n+1)*129 + m + 8] = acc[mi][nj][3] + f1;
        }
    }
    __syncthreads();
    size_t base = (size_t)bh*NDH*NT;
    for (int i = tid; i < 4096; i += 256) {
        int d = i >> 6, mm = (i & 63)*2;
        uint32_t hi, lo;
        split2(Sg[d*129 + mm], Sg[d*129 + mm + 1], hi, lo);
        size_t idx = base + (size_t)d*NT + t0 + mm;
        *(uint32_t*)(g_VFth + idx) = hi;
        *(uint32_t*)(g_VFtl + idx) = lo;
    }
}

// ---------------------------------------------------------------------------
// k_attn_fused (restructured for occupancy 2): scores -> softmax -> attn ->
// P as bf16 frags -> P·VF in two d-halves -> HO split.
// grid (16, BH), block 256, dyn smem 84992, __launch_bounds__(256,2)
// ---------------------------------------------------------------------------
__global__ void __launch_bounds__(256, 2) k_attn_fused(float* __restrict__ attn_out)
{
    extern __shared__ uint32_t sm32[];
    float* sredm = (float*)(sm32 + 20736);
    float* sreds = (float*)(sm32 + 20992);
    int tid = threadIdx.x, wid = tid >> 5, lane = tid & 31;
    int g = lane >> 2, t4 = lane & 3;
    int s0 = blockIdx.x << 5, bh = blockIdx.y;

    uint32_t sb = smem_u32(sm32);
    uint32_t lrow = lane & 15, lsel = (lane >> 4) << 4;
    uint32_t aoffH = sb + 73728 + lrow*A_STRIDE_B + lsel;
    uint32_t aoffL = aoffH + 4608;
    uint32_t boffH = sb + (wid*32 + lrow)*A_STRIDE_B + lsel;
    uint32_t boffL = boffH + 36864;

    const uint4* gQ4h = (const uint4*)(g_Qh + ((size_t)bh*NS + s0)*NDH);
    const uint4* gQ4l = (const uint4*)(g_Ql + ((size_t)bh*NS + s0)*NDH);
    {
        int r = tid >> 3, c = tid & 7;
        *(uint4*)&sm32[18432 + r*36 + c*4] = gQ4h[(size_t)r*8 + c];
        *(uint4*)&sm32[19584 + r*36 + c*4] = gQ4l[(size_t)r*8 + c];
    }

    float acc[2][8][4];
#pragma unroll
    for (int mi = 0; mi < 2; mi++)
#pragma unroll
        for (int nj = 0; nj < 8; nj++)
#pragma unroll
            for (int q = 0; q < 4; q++) acc[mi][nj][q] = 0.f;

    const uint4* gKE4h = (const uint4*)(g_KEh + (size_t)bh*NT*NDH);
    const uint4* gKE4l = (const uint4*)(g_KEl + (size_t)bh*NT*NDH);

    for (int chn = 0; chn < 2; chn++) {
        if (chn) __syncthreads();
        for (int i = tid; i < 2048; i += 256) {
            int r = i >> 3, c = i & 7;
            *(uint4*)&sm32[r*36 + c*4]        = gKE4h[(size_t)(chn*256 + r)*8 + c];
            *(uint4*)&sm32[9216 + r*36 + c*4] = gKE4l[(size_t)(chn*256 + r)*8 + c];
        }
        __syncthreads();
#pragma unroll
        for (int ks = 0; ks < 4; ks++) {
            uint32_t ah[2][4], al[2][4];
#pragma unroll
            for (int mi = 0; mi < 2; mi++) {
                ldmx4(ah[mi][0],ah[mi][1],ah[mi][2],ah[mi][3], aoffH + mi*MI_STEP_B + ks*KS_STEP_B);
                ldmx4(al[mi][0],al[mi][1],al[mi][2],al[mi][3], aoffL + mi*MI_STEP_B + ks*KS_STEP_B);
            }
#pragma unroll
            for (int nj2 = 0; nj2 < 2; nj2++) {
                uint32_t bhp[4], blp[4];
                ldmx4(bhp[0],bhp[1],bhp[2],bhp[3], boffH + nj2*MI_STEP_B + ks*KS_STEP_B);
                ldmx4(blp[0],blp[1],blp[2],blp[3], boffL + nj2*MI_STEP_B + ks*KS_STEP_B);
#pragma unroll
                for (int jj = 0; jj < 2; jj++) {
                    int nj = chn*4 + nj2*2 + jj;
#pragma unroll
                    for (int mi = 0; mi < 2; mi++) {
                        mma16816(acc[mi][nj], ah[mi][0],ah[mi][1],ah[mi][2],ah[mi][3], bhp[jj], bhp[jj+2]);
                        mma16816(acc[mi][nj], ah[mi][0],ah[mi][1],ah[mi][2],ah[mi][3], blp[jj], blp[jj+2]);
                        mma16816(acc[mi][nj], al[mi][0],al[mi][1],al[mi][2],al[mi][3], bhp[jj], bhp[jj+2]);
                    }
                }
            }
        }
    }

    // ---- softmax ----
    float lm[2][2];
#pragma unroll
    for (int mi = 0; mi < 2; mi++) { lm[mi][0] = -1e30f; lm[mi][1] = -1e30f; }
#pragma unroll
    for (int mi = 0; mi < 2; mi++)
#pragma unroll
        for (int nj = 0; nj < 8; nj++) {
#pragma unroll
            for (int q = 0; q < 4; q++) acc[mi][nj][q] *= 0.125f;
            lm[mi][0] = fmaxf(lm[mi][0], fmaxf(acc[mi][nj][0], acc[mi][nj][1]));
            lm[mi][1] = fmaxf(lm[mi][1], fmaxf(acc[mi][nj][2], acc[mi][nj][3]));
        }
#pragma unroll
    for (int mi = 0; mi < 2; mi++)
#pragma unroll
        for (int hh = 0; hh < 2; hh++) {
            lm[mi][hh] = fmaxf(lm[mi][hh], __shfl_xor_sync(0xffffffffu, lm[mi][hh], 1));
            lm[mi][hh] = fmaxf(lm[mi][hh], __shfl_xor_sync(0xffffffffu, lm[mi][hh], 2));
        }
    if (t4 == 0) {
#pragma unroll
        for (int mi = 0; mi < 2; mi++) {
            sredm[wid*32 + mi*16 + g]     = lm[mi][0];
            sredm[wid*32 + mi*16 + g + 8] = lm[mi][1];
        }
    }
    __syncthreads();
    float rowm[2][2];
#pragma unroll
    for (int mi = 0; mi < 2; mi++)
#pragma unroll
        for (int hh = 0; hh < 2; hh++) {
            int row = mi*16 + g + hh*8;
            float m = sredm[row];
#pragma unroll
            for (int w = 1; w < 8; w++) m = fmaxf(m, sredm[w*32 + row]);
            rowm[mi][hh] = m;
        }
    float ls[2][2] = {{0.f,0.f},{0.f,0.f}};
#pragma unroll
    for (int mi = 0; mi < 2; mi++)
#pragma unroll
        for (int nj = 0; nj < 8; nj++) {
            acc[mi][nj][0] = __expf(acc[mi][nj][0] - rowm[mi][0]);
            acc[mi][nj][1] = __expf(acc[mi][nj][1] - rowm[mi][0]);
            acc[mi][nj][2] = __expf(acc[mi][nj][2] - rowm[mi][1]);
            acc[mi][nj][3] = __expf(acc[mi][nj][3] - rowm[mi][1]);
            ls[mi][0] += acc[mi][nj][0] + acc[mi][nj][1];
            ls[mi][1] += acc[mi][nj][2] + acc[mi][nj][3];
        }
#pragma unroll
    for (int mi = 0; mi < 2; mi++)
#pragma unroll
        for (int hh = 0; hh < 2; hh++) {
            ls[mi][hh] += __shfl_xor_sync(0xffffffffu, ls[mi][hh], 1);
            ls[mi][hh] += __shfl_xor_sync(0xffffffffu, ls[mi][hh], 2);
        }
    if (t4 == 0) {
#pragma unroll
        for (int mi = 0; mi < 2; mi++) {
            sreds[wid*32 + mi*16 + g]     = ls[mi][0];
            sreds[wid*32 + mi*16 + g + 8] = ls[mi][1];
        }
    }
    __syncthreads();
    float inv[2][2];
#pragma unroll
    for (int mi = 0; mi < 2; mi++)
#pragma unroll
        for (int hh = 0; hh < 2; hh++) {
            int row = mi*16 + g + hh*8;
            float s = 0.f;
#pragma unroll
            for (int w = 0; w < 8; w++) s += sreds[w*32 + row];
            inv[mi][hh] = 1.f / s;
        }

    // normalize, write attn, convert P -> bf16 split fragments (frees fp32 acc)
    uint32_t pah[4][2][4], pal[4][2][4];   // [kstep][mi][4]
#pragma unroll
    for (int hf = 0; hf < 2; hf++)
#pragma unroll
        for (int ks2 = 0; ks2 < 2; ks2++) {
            int ke = hf*2 + ks2;
#pragma unroll
            for (int mi = 0; mi < 2; mi++) {
                int nj0 = hf*4 + ks2*2, nj1 = nj0 + 1;
                size_t r0 = ((size_t)bh*NS + s0 + mi*16 + g)*NT;
                size_t r1 = r0 + 8*NT;
                int c0 = hf*256 + wid*32 + ks2*16 + 2*t4;
                acc[mi][nj0][0] *= inv[mi][0];  acc[mi][nj0][1] *= inv[mi][0];
                acc[mi][nj0][2] *= inv[mi][1];  acc[mi][nj0][3] *= inv[mi][1];
                acc[mi][nj1][0] *= inv[mi][0];  acc[mi][nj1][1] *= inv[mi][0];
                acc[mi][nj1][2] *= inv[mi][1];  acc[mi][nj1][3] *= inv[mi][1];
                *(float2*)(attn_out + r0 + c0)     = make_float2(acc[mi][nj0][0], acc[mi][nj0][1]);
                *(float2*)(attn_out + r1 + c0)     = make_float2(acc[mi][nj0][2], acc[mi][nj0][3]);
                *(float2*)(attn_out + r0 + c0 + 8) = make_float2(acc[mi][nj1][0], acc[mi][nj1][1]);
                *(float2*)(attn_out + r1 + c0 + 8) = make_float2(acc[mi][nj1][2], acc[mi][nj1][3]);
                split2(acc[mi][nj0][0], acc[mi][nj0][1], pah[ke][mi][0], pal[ke][mi][0]);
                split2(acc[mi][nj0][2], acc[mi][nj0][3], pah[ke][mi][1], pal[ke][mi][1]);
                split2(acc[mi][nj1][0], acc[mi][nj1][1], pah[ke][mi][2], pal[ke][mi][2]);
                split2(acc[mi][nj1][2], acc[mi][nj1][3], pah[ke][mi][3], pal[ke][mi][3]);
            }
        }

    // ---- P·VF in two d-halves (acc_o only 32 regs live) ----
    const uint4* gVF4h = (const uint4*)(g_VFth + (size_t)bh*NDH*NT);
    const uint4* gVF4l = (const uint4*)(g_VFtl + (size_t)bh*NDH*NT);
    uint32_t b_pvH = sb + lrow*528 + wid*64 + lsel;
    uint32_t b_pvL = b_pvH + 16896;

    for (int dh = 0; dh < 2; dh++) {
        float acc_o[2][4][4];
#pragma unroll
        for (int mi = 0; mi < 2; mi++)
#pragma unroll
            for (int nd = 0; nd < 4; nd++)
#pragma unroll
                for (int q = 0; q < 4; q++) acc_o[mi][nd][q] = 0.f;

        for (int hf = 0; hf < 2; hf++) {
            __syncthreads();
            for (int i = tid; i < 1024; i += 256) {
                int r = i >> 5, c = i & 31;
                *(uint4*)&sm32[r*132 + c*4]        = gVF4h[(size_t)(dh*32 + r)*64 + hf*32 + c];
                *(uint4*)&sm32[4224 + r*132 + c*4] = gVF4l[(size_t)(dh*32 + r)*64 + hf*32 + c];
            }
            __syncthreads();
#pragma unroll
            for (int dt = 0; dt < 2; dt++) {
#pragma unroll
                for (int ks2 = 0; ks2 < 2; ks2++) {
                    int ke = hf*2 + ks2;
                    uint32_t bhv[4], blv[4];
                    ldmx4(bhv[0],bhv[1],bhv[2],bhv[3], b_pvH + dt*8448 + ks2*32);
                    ldmx4(blv[0],blv[1],blv[2],blv[3], b_pvL + dt*8448 + ks2*32);
#pragma unroll
                    for (int jj = 0; jj < 2; jj++) {
                        int nd = dt*2 + jj;
#pragma unroll
                        for (int mi = 0; mi < 2; mi++) {
                            mma16816(acc_o[mi][nd], pah[ke][mi][0],pah[ke][mi][1],pah[ke][mi][2],pah[ke][mi][3], bhv[jj], bhv[jj+2]);
                            mma16816(acc_o[mi][nd], pah[ke][mi][0],pah[ke][mi][1],pah[ke][mi][2],pah[ke][mi][3], blv[jj], blv[jj+2]);
                            mma16816(acc_o[mi][nd], pal[ke][mi][0],pal[ke][mi][1],pal[ke][mi][2],pal[ke][mi][3], bhv[jj], bhv[jj+2]);
                        }
                    }
                }
            }
        }

        // cross-warp reduction for this d-half
        __syncthreads();
        float* Ob = (float*)sm32;   // [8][32][33]
#pragma unroll
        for (int mi = 0; mi < 2; mi++)
#pragma unroll
            for (int nd = 0; nd < 4; nd++) {
                int m = mi*16 + g, n = nd*8 + 2*t4;
                Ob[wid*1056 + m*33 + n]       = acc_o[mi][nd][0];
                Ob[wid*1056 + m*33 + n + 1]   = acc_o[mi][nd][1];
                Ob[wid*1056 + (m+8)*33 + n]   = acc_o[mi][nd][2];
                Ob[wid*1056 + (m+8)*33 + n+1] = acc_o[mi][nd][3];
            }
        __syncthreads();
        {
            int s = tid >> 3, dg = (tid & 7)*4;
            float o[4] = {0.f, 0.f, 0.f, 0.f};
#pragma unroll
            for (int w = 0; w < 8; w++)
#pragma unroll
                for (int j = 0; j < 4; j++) o[j] += Ob[w*1056 + s*33 + dg + j];
            size_t base = ((size_t)bh*NS + s0 + s)*NDH + dh*32 + dg;
            uint32_t hi, lo;
            split2(o[0], o[1], hi, lo);
            *(uint32_t*)(g_HOh + base) = hi;     *(uint32_t*)(g_HOl + base) = lo;
            split2(o[2], o[3], hi, lo);
            *(uint32_t*)(g_HOh + base + 2) = hi; *(uint32_t*)(g_HOl + base + 2) = lo;
        }
    }
}

// ---------------------------------------------------------------------------
// k_out_mma (unchanged)
// ---------------------------------------------------------------------------
__global__ void __launch_bounds__(256, 2) k_out_mma(const float* __restrict__ Ob,
                                                    float* __restrict__ out)
{
    extern __shared__ uint32_t sm32[];
    int tid = threadIdx.x, wid = tid >> 5, lane = tid & 31;
    int g = lane >> 2, t4 = lane & 3;
    int m0w = (wid & 3)*32, n0w = (wid >> 2)*32;
    int m0 = blockIdx.x << 7;
    int b  = blockIdx.x >> 2;
    int sbase = (blockIdx.x & 3) << 7;
    int n0 = blockIdx.y << 6;

    uint32_t sb = smem_u32(sm32);
    uint32_t lrow = lane & 15, lsel = (lane >> 4) << 4;
    uint32_t aoffH = sb + (m0w + lrow)*A_STRIDE_B + lsel;
    uint32_t aoffL = aoffH + 18432;
    uint32_t boffH = sb + 36864 + (n0w + lrow)*A_STRIDE_B + lsel;
    uint32_t boffL = boffH + 9216;

    float acc[2][4][4];
#pragma unroll
    for (int mi = 0; mi < 2; mi++)
#pragma unroll
        for (int nj = 0; nj < 4; nj++)
#pragma unroll
            for (int q = 0; q < 4; q++) acc[mi][nj][q] = 0.f;

    for (int kc = 0; kc < 16; kc++) {
        const uint4* gA4h = (const uint4*)(g_HOh + ((size_t)(b*NH + kc)*NS + sbase)*NDH);
        const uint4* gA4l = (const uint4*)(g_HOl + ((size_t)(b*NH + kc)*NS + sbase)*NDH);
        const uint4* gB4h = (const uint4*)(g_Owh + (size_t)n0*NDM);
        const uint4* gB4l = (const uint4*)(g_Owl + (size_t)n0*NDM);
        __syncthreads();
        for (int i = tid; i < 1024; i += 256) {
            int r = i >> 3, c = i & 7;
            *(uint4*)&sm32[r*36 + c*4]        = gA4h[(size_t)r*8 + c];
            *(uint4*)&sm32[4608 + r*36 + c*4] = gA4l[(size_t)r*8 + c];
        }
        for (int i = tid; i < 512; i += 256) {
            int r = i >> 3, c = i & 7;
            *(uint4*)&sm32[9216 + r*36 + c*4]  = gB4h[(size_t)r*128 + kc*8 + c];
            *(uint4*)&sm32[11520 + r*36 + c*4] = gB4l[(size_t)r*128 + kc*8 + c];
        }
        __syncthreads();
        MMA_CHUNK_LDSM();
    }

    __syncthreads();
    float* Sg = (float*)sm32;
#pragma unroll
    for (int mi = 0; mi < 2; mi++) {
        int m = m0w + mi*16 + g;
#pragma unroll
        for (int nj = 0; nj < 4; nj++) {
            int n = n0w + nj*8 + t4*2;
            float o0 = Ob[n0 + n];
            float o1 = Ob[n0 + n + 1];
            Sg[m*65 + n]         = acc[mi][nj][0] + o0;
            Sg[m*65 + n + 1]     = acc[mi][nj][1] + o1;
            Sg[(m+8)*65 + n]     = acc[mi][nj][2] + o0;
            Sg[(m+8)*65 + n + 1] = acc[mi][nj][3] + o1;
        }
    }
    __syncthreads();
    for (int i = tid; i < 8192; i += 256) {
        int r = i >> 6, c = i & 63;
        out[(size_t)(m0 + r)*NDM + n0 + c] = Sg[r*65 + c];
    }
}

// ---------------------------------------------------------------------------
extern "C" void kernel_launch(void* const* d_in, const int* in_sizes, int n_in,
                              void* d_out, int out_size)
{
    const float* query = (const float*)d_in[0];
    const float* key   = (const float*)d_in[1];
    const float* value = (const float*)d_in[2];
    const float* Wq    = (const float*)d_in[3];
    const float* bq    = (const float*)d_in[4];
    const float* Wk    = (const float*)d_in[5];
    const float* bk    = (const float*)d_in[6];
    const float* Wv    = (const float*)d_in[7];
    const float* bv    = (const float*)d_in[8];
    const float* E_w   = (const float*)d_in[9];
    const float* E_b   = (const float*)d_in[10];
    const float* F_w   = (const float*)d_in[11];
    const float* F_b   = (const float*)d_in[12];
    const float* out_w = (const float*)d_in[13];
    const float* out_b = (const float*)d_in[14];

    const long long mha_elems  = (long long)NB*NS*NDM;
    const long long attn_elems = (long long)BH*NS*NT;

    float* outp = (float*)d_out;
    float* mha_ptr;
    float* attn_ptr;
    if ((long long)out_size >= mha_elems + attn_elems) {
        mha_ptr  = outp;
        attn_ptr = outp + mha_elems;
    } else if ((long long)out_size == attn_elems) {
        attn_ptr = outp;
        cudaGetSymbolAddress((void**)&mha_ptr, g_MHA_FB);
    } else {
        mha_ptr = outp;
        cudaGetSymbolAddress((void**)&attn_ptr, g_ATTN_FB);
    }

    cudaFuncSetAttribute(k_qkv_mma,    cudaFuncAttributeMaxDynamicSharedMemorySize, 55296);
    cudaFuncSetAttribute(k_ke_mma,     cudaFuncAttributeMaxDynamicSharedMemorySize, 55296);
    cudaFuncSetAttribute(k_vf_mma,     cudaFuncAttributeMaxDynamicSharedMemorySize, 55296);
    cudaFuncSetAttribute(k_out_mma,    cudaFuncAttributeMaxDynamicSharedMemorySize, 55296);
    cudaFuncSetAttribute(k_attn_fused, cudaFuncAttributeMaxDynamicSharedMemorySize, 84992);

    // launch order chosen so ncu (-s 5 -c 1) profiles k_attn_fused (launch #6)
    k_split6<<<(3*NX + 3*NW + 255)/256, 256>>>(query, key, value, Wq, Wk, Wv);
    k_split3<<<(2*NT*NS + NDM*NDM + 255)/256, 256>>>(E_w, F_w, out_w);
    k_qkv_mma<<<dim3(BH, 4, 3), 256, 55296>>>(bq, bk, bv);
    k_ke_mma<<<dim3(BH, 4), 256, 55296>>>(E_b);
    k_vf_mma<<<dim3(BH, 4), 256, 55296>>>(F_b);
    k_attn_fused<<<dim3(16, BH), 256, 84992>>>(attn_ptr);
    k_out_mma<<<dim3((NB*NS)/128, NDM/64), 256, 55296>>>(out_b, mha_ptr);
}

// round 9
// speedup vs baseline: 2.6830x; 1.3075x over previous
#include <cuda_runtime.h>
#include <cuda_bf16.h>
#include <cstdint>

#define NB 32
#define NS 512
#define NH 16
#define NDH 64
#define NDM 1024
#define NT 512
#define BH (NB*NH)

// ---------------- global scratch ----------------
__device__ __nv_bfloat16 g_Xqh[NB*NS*NDH], g_Xql[NB*NS*NDH];
__device__ __nv_bfloat16 g_Xkh[NB*NS*NDH], g_Xkl[NB*NS*NDH];
__device__ __nv_bfloat16 g_Xvh[NB*NS*NDH], g_Xvl[NB*NS*NDH];
__device__ __nv_bfloat16 g_Wqh[NH*NDH*NDH], g_Wql[NH*NDH*NDH];
__device__ __nv_bfloat16 g_Wkh[NH*NDH*NDH], g_Wkl[NH*NDH*NDH];
__device__ __nv_bfloat16 g_Wvh[NH*NDH*NDH], g_Wvl[NH*NDH*NDH];
__device__ __nv_bfloat16 g_Qh [(size_t)BH*NS*NDH];
__device__ __nv_bfloat16 g_Ql [(size_t)BH*NS*NDH];
__device__ __nv_bfloat16 g_Kth[(size_t)BH*NDH*NS];
__device__ __nv_bfloat16 g_Ktl[(size_t)BH*NDH*NS];
__device__ __nv_bfloat16 g_Vth[(size_t)BH*NDH*NS];
__device__ __nv_bfloat16 g_Vtl[(size_t)BH*NDH*NS];
__device__ __nv_bfloat16 g_KEh[(size_t)BH*NT*NDH];
__device__ __nv_bfloat16 g_KEl[(size_t)BH*NT*NDH];
__device__ __nv_bfloat16 g_VFth[(size_t)BH*NDH*NT];
__device__ __nv_bfloat16 g_VFtl[(size_t)BH*NDH*NT];
__device__ __nv_bfloat16 g_Ewh[NT*NS], g_Ewl[NT*NS];
__device__ __nv_bfloat16 g_Fwh[NT*NS], g_Fwl[NT*NS];
__device__ __nv_bfloat16 g_Owh[NDM*NDM], g_Owl[NDM*NDM];
__device__ __nv_bfloat16 g_HOh[(size_t)BH*NS*NDH];
__device__ __nv_bfloat16 g_HOl[(size_t)BH*NS*NDH];
__device__ float g_ATTN_FB[(size_t)BH*NS*NT];
__device__ float g_MHA_FB [(size_t)NB*NS*NDM];

// ---------------- helpers ----------------
__device__ __forceinline__ uint32_t smem_u32(const void* p) {
    uint32_t a;
    asm("{ .reg .u64 t; cvta.to.shared.u64 t, %1; cvt.u32.u64 %0, t; }" : "=r"(a) : "l"(p));
    return a;
}
__device__ __forceinline__ void mma16816(float c[4],
                                         uint32_t a0, uint32_t a1, uint32_t a2, uint32_t a3,
                                         uint32_t b0, uint32_t b1)
{
    asm volatile(
        "mma.sync.aligned.m16n8k16.row.col.f32.bf16.bf16.f32 "
        "{%0,%1,%2,%3}, {%4,%5,%6,%7}, {%8,%9}, {%0,%1,%2,%3};"
        : "+f"(c[0]), "+f"(c[1]), "+f"(c[2]), "+f"(c[3])
        : "r"(a0), "r"(a1), "r"(a2), "r"(a3), "r"(b0), "r"(b1));
}
__device__ __forceinline__ void ldmx4(uint32_t& r0, uint32_t& r1, uint32_t& r2, uint32_t& r3,
                                      uint32_t addr)
{
    asm volatile("ldmatrix.sync.aligned.m8n8.x4.shared.b16 {%0,%1,%2,%3}, [%4];"
                 : "=r"(r0), "=r"(r1), "=r"(r2), "=r"(r3) : "r"(addr));
}
__device__ __forceinline__ void cp16(uint32_t saddr, const void* g)
{
    asm volatile("cp.async.cg.shared.global [%0], [%1], 16;" :: "r"(saddr), "l"(g) : "memory");
}
__device__ __forceinline__ void cp_wait()
{
    asm volatile("cp.async.commit_group;\n\tcp.async.wait_group 0;" ::: "memory");
}
__device__ __forceinline__ void split2(float x, float y, uint32_t& hi, uint32_t& lo)
{
    __nv_bfloat162 h = __floats2bfloat162_rn(x, y);
    float hx = __bfloat162float(h.x), hy = __bfloat162float(h.y);
    __nv_bfloat162 l = __floats2bfloat162_rn(x - hx, y - hy);
    hi = *(uint32_t*)&h;
    lo = *(uint32_t*)&l;
}
__device__ __forceinline__ void split_store(float v, __nv_bfloat16* h, __nv_bfloat16* l, int i)
{
    __nv_bfloat16 hb = __float2bfloat16(v);
    h[i] = hb;
    l[i] = __float2bfloat16(v - __bfloat162float(hb));
}

// smem geometry (u32 units): row stride 36 words (144B)
#define A_STRIDE_B 144
#define MI_STEP_B  2304
#define KS_STEP_B  32

#define MMA_CHUNK_LDSM()                                                          \
    _Pragma("unroll")                                                             \
    for (int ks = 0; ks < 4; ks++) {                                              \
        uint32_t ah[2][4], al[2][4];                                              \
        _Pragma("unroll")                                                         \
        for (int mi = 0; mi < 2; mi++) {                                          \
            ldmx4(ah[mi][0],ah[mi][1],ah[mi][2],ah[mi][3], aoffH + mi*MI_STEP_B + ks*KS_STEP_B); \
            ldmx4(al[mi][0],al[mi][1],al[mi][2],al[mi][3], aoffL + mi*MI_STEP_B + ks*KS_STEP_B); \
        }                                                                         \
        _Pragma("unroll")                                                         \
        for (int nj2 = 0; nj2 < 2; nj2++) {                                       \
            uint32_t bh[4], bl[4];                                                \
            ldmx4(bh[0],bh[1],bh[2],bh[3], boffH + nj2*MI_STEP_B + ks*KS_STEP_B); \
            ldmx4(bl[0],bl[1],bl[2],bl[3], boffL + nj2*MI_STEP_B + ks*KS_STEP_B); \
            _Pragma("unroll")                                                     \
            for (int jj = 0; jj < 2; jj++) {                                      \
                int nj = nj2*2 + jj;                                              \
                _Pragma("unroll")                                                 \
                for (int mi = 0; mi < 2; mi++) {                                  \
                    mma16816(acc[mi][nj], ah[mi][0],ah[mi][1],ah[mi][2],ah[mi][3], bh[jj], bh[jj+2]); \
                    mma16816(acc[mi][nj], ah[mi][0],ah[mi][1],ah[mi][2],ah[mi][3], bl[jj], bl[jj+2]); \
                    mma16816(acc[mi][nj], al[mi][0],al[mi][1],al[mi][2],al[mi][3], bh[jj], bh[jj+2]); \
                }                                                                 \
            }                                                                     \
        }                                                                         \
    }

// ---------------------------------------------------------------------------
// combined split kernels
// ---------------------------------------------------------------------------
#define NX (NB*NS*NDH)
#define NW (NH*NDH*NDH)
__global__ void k_split6(const float* __restrict__ xq, const float* __restrict__ xk,
                         const float* __restrict__ xv, const float* __restrict__ wq,
                         const float* __restrict__ wk, const float* __restrict__ wv)
{
    int i = blockIdx.x*256 + threadIdx.x;
    if (i < NX)                  split_store(xq[i], g_Xqh, g_Xql, i);
    else if (i < 2*NX)           split_store(xk[i - NX], g_Xkh, g_Xkl, i - NX);
    else if (i < 3*NX)           split_store(xv[i - 2*NX], g_Xvh, g_Xvl, i - 2*NX);
    else if (i < 3*NX + NW)      split_store(wq[i - 3*NX], g_Wqh, g_Wql, i - 3*NX);
    else if (i < 3*NX + 2*NW)    split_store(wk[i - 3*NX - NW], g_Wkh, g_Wkl, i - 3*NX - NW);
    else if (i < 3*NX + 3*NW)    split_store(wv[i - 3*NX - 2*NW], g_Wvh, g_Wvl, i - 3*NX - 2*NW);
}
__global__ void k_split3(const float* __restrict__ ew, const float* __restrict__ fw,
                         const float* __restrict__ ow)
{
    const int NE = NT*NS;
    int i = blockIdx.x*256 + threadIdx.x;
    if (i < NE)                  split_store(ew[i], g_Ewh, g_Ewl, i);
    else if (i < 2*NE)           split_store(fw[i - NE], g_Fwh, g_Fwl, i - NE);
    else if (i < 2*NE + NDM*NDM) split_store(ow[i - 2*NE], g_Owh, g_Owl, i - 2*NE);
}

// ---------------------------------------------------------------------------
// k_qkv_mma
// ---------------------------------------------------------------------------
__global__ void __launch_bounds__(256, 3) k_qkv_mma(const float* __restrict__ bq,
                                                    const float* __restrict__ bk,
                                                    const float* __restrict__ bv)
{
    extern __shared__ uint32_t sm32[];
    int tid = threadIdx.x, wid = tid >> 5, lane = tid & 31;
    int g = lane >> 2, t4 = lane & 3;
    int m0w = (wid & 3)*32, n0w = (wid >> 2)*32;
    int bh = blockIdx.x, b = bh >> 4, h = bh & 15;
    int s0 = blockIdx.y << 7, z = blockIdx.z;

    uint32_t sb = smem_u32(sm32);
    uint32_t lrow = lane & 15, lsel = (lane >> 4) << 4;
    uint32_t aoffH = sb + (m0w + lrow)*A_STRIDE_B + lsel;
    uint32_t aoffL = aoffH + 18432;
    uint32_t boffH = sb + 36864 + (n0w + lrow)*A_STRIDE_B + lsel;
    uint32_t boffL = boffH + 9216;

    const uint4 *gA4h, *gA4l, *gB4h, *gB4l;
    const float* bias;
    if (z == 0)      { gA4h = (const uint4*)(g_Xqh + ((size_t)b*NS + s0)*NDH);
                       gA4l = (const uint4*)(g_Xql + ((size_t)b*NS + s0)*NDH);
                       gB4h = (const uint4*)(g_Wqh + h*4096);
                       gB4l = (const uint4*)(g_Wql + h*4096); bias = bq + h*64; }
    else if (z == 1) { gA4h = (const uint4*)(g_Xkh + ((size_t)b*NS + s0)*NDH);
                       gA4l = (const uint4*)(g_Xkl + ((size_t)b*NS + s0)*NDH);
                       gB4h = (const uint4*)(g_Wkh + h*4096);
                       gB4l = (const uint4*)(g_Wkl + h*4096); bias = bk + h*64; }
    else             { gA4h = (const uint4*)(g_Xvh + ((size_t)b*NS + s0)*NDH);
                       gA4l = (const uint4*)(g_Xvl + ((size_t)b*NS + s0)*NDH);
                       gB4h = (const uint4*)(g_Wvh + h*4096);
                       gB4l = (const uint4*)(g_Wvl + h*4096); bias = bv + h*64; }

    float acc[2][4][4];
#pragma unroll
    for (int mi = 0; mi < 2; mi++)
#pragma unroll
        for (int nj = 0; nj < 4; nj++)
#pragma unroll
            for (int q = 0; q < 4; q++) acc[mi][nj][q] = 0.f;

    for (int i = tid; i < 1024; i += 256) {
        int r = i >> 3, c = i & 7;
        cp16(sb + (r*36 + c*4)*4,          gA4h + (size_t)r*8 + c);
        cp16(sb + (4608 + r*36 + c*4)*4,   gA4l + (size_t)r*8 + c);
    }
    for (int i = tid; i < 512; i += 256) {
        int r = i >> 3, c = i & 7;
        cp16(sb + (9216 + r*36 + c*4)*4,   gB4h + (size_t)r*8 + c);
        cp16(sb + (11520 + r*36 + c*4)*4,  gB4l + (size_t)r*8 + c);
    }
    cp_wait();
    __syncthreads();
    MMA_CHUNK_LDSM();

    if (z == 0) {
        size_t base = (size_t)bh*NS*NDH;
#pragma unroll
        for (int mi = 0; mi < 2; mi++) {
            int m = m0w + mi*16 + g;
#pragma unroll
            for (int nj = 0; nj < 4; nj++) {
                int n = n0w + nj*8 + t4*2;
                float b0 = bias[n], b1 = bias[n + 1];
                uint32_t hi, lo;
                size_t i0 = base + (size_t)(s0 + m)*NDH + n;
                split2(acc[mi][nj][0] + b0, acc[mi][nj][1] + b1, hi, lo);
                *(uint32_t*)(g_Qh + i0) = hi;  *(uint32_t*)(g_Ql + i0) = lo;
                size_t i1 = base + (size_t)(s0 + m + 8)*NDH + n;
                split2(acc[mi][nj][2] + b0, acc[mi][nj][3] + b1, hi, lo);
                *(uint32_t*)(g_Qh + i1) = hi;  *(uint32_t*)(g_Ql + i1) = lo;
            }
        }
    } else {
        __syncthreads();
        float* Sg = (float*)sm32;
#pragma unroll
        for (int mi = 0; mi < 2; mi++) {
            int m = m0w + mi*16 + g;
#pragma unroll
            for (int nj = 0; nj < 4; nj++) {
                int n = n0w + nj*8 + t4*2;
                float b0 = bias[n], b1 = bias[n + 1];
                Sg[n*129 + m]         = acc[mi][nj][0] + b0;
                Sg[(n+1)*129 + m]     = acc[mi][nj][1] + b1;
                Sg[n*129 + m + 8]     = acc[mi][nj][2] + b0;
                Sg[(n+1)*129 + m + 8] = acc[mi][nj][3] + b1;
            }
        }
        __syncthreads();
        __nv_bfloat16* dh = (z == 1 ? g_Kth : g_Vth);
        __nv_bfloat16* dl = (z == 1 ? g_Ktl : g_Vtl);
        size_t base = (size_t)bh*NDH*NS;
        for (int i = tid; i < 4096; i += 256) {
            int d = i >> 6, mm = (i & 63)*2;
            uint32_t hi, lo;
            split2(Sg[d*129 + mm], Sg[d*129 + mm + 1], hi, lo);
            size_t idx = base + (size_t)d*NS + s0 + mm;
            *(uint32_t*)(dh + idx) = hi;
            *(uint32_t*)(dl + idx) = lo;
        }
    }
}

// ---------------------------------------------------------------------------
// k_ke_mma
// ---------------------------------------------------------------------------
__global__ void __launch_bounds__(256, 3) k_ke_mma(const float* __restrict__ Eb)
{
    extern __shared__ uint32_t sm32[];
    int tid = threadIdx.x, wid = tid >> 5, lane = tid & 31;
    int g = lane >> 2, t4 = lane & 3;
    int m0w = (wid & 3)*32, n0w = (wid >> 2)*32;
    int bh = blockIdx.x, t0 = blockIdx.y << 7;

    uint32_t sb = smem_u32(sm32);
    uint32_t lrow = lane & 15, lsel = (lane >> 4) << 4;
    uint32_t aoffH = sb + (m0w + lrow)*A_STRIDE_B + lsel;
    uint32_t aoffL = aoffH + 18432;
    uint32_t boffH = sb + 36864 + (n0w + lrow)*A_STRIDE_B + lsel;
    uint32_t boffL = boffH + 9216;

    float acc[2][4][4];
#pragma unroll
    for (int mi = 0; mi < 2; mi++)
#pragma unroll
        for (int nj = 0; nj < 4; nj++)
#pragma unroll
            for (int q = 0; q < 4; q++) acc[mi][nj][q] = 0.f;

    const uint4* gA4h = (const uint4*)(g_Ewh + (size_t)t0*NS);
    const uint4* gA4l = (const uint4*)(g_Ewl + (size_t)t0*NS);
    const uint4* gB4h = (const uint4*)(g_Kth + (size_t)bh*NDH*NS);
    const uint4* gB4l = (const uint4*)(g_Ktl + (size_t)bh*NDH*NS);

    for (int ch = 0; ch < 8; ch++) {
        __syncthreads();
        for (int i = tid; i < 1024; i += 256) {
            int r = i >> 3, c = i & 7;
            cp16(sb + (r*36 + c*4)*4,        gA4h + (size_t)r*64 + ch*8 + c);
            cp16(sb + (4608 + r*36 + c*4)*4, gA4l + (size_t)r*64 + ch*8 + c);
        }
        for (int i = tid; i < 512; i += 256) {
            int r = i >> 3, c = i & 7;
            cp16(sb + (9216 + r*36 + c*4)*4,  gB4h + (size_t)r*64 + ch*8 + c);
            cp16(sb + (11520 + r*36 + c*4)*4, gB4l + (size_t)r*64 + ch*8 + c);
        }
        cp_wait();
        __syncthreads();
        MMA_CHUNK_LDSM();
    }

    size_t base = (size_t)bh*NT*NDH;
#pragma unroll
    for (int mi = 0; mi < 2; mi++) {
        int m = m0w + mi*16 + g;
        float e0 = Eb[t0 + m];
        float e1 = Eb[t0 + m + 8];
#pragma unroll
        for (int nj = 0; nj < 4; nj++) {
            int n = n0w + nj*8 + t4*2;
            uint32_t hi, lo;
            size_t i0 = base + (size_t)(t0 + m)*NDH + n;
            split2(acc[mi][nj][0] + e0, acc[mi][nj][1] + e0, hi, lo);
            *(uint32_t*)(g_KEh + i0) = hi;  *(uint32_t*)(g_KEl + i0) = lo;
            size_t i1 = base + (size_t)(t0 + m + 8)*NDH + n;
            split2(acc[mi][nj][2] + e1, acc[mi][nj][3] + e1, hi, lo);
            *(uint32_t*)(g_KEh + i1) = hi;  *(uint32_t*)(g_KEl + i1) = lo;
        }
    }
}

// ---------------------------------------------------------------------------
// k_vf_mma
// ---------------------------------------------------------------------------
__global__ void __launch_bounds__(256, 3) k_vf_mma(const float* __restrict__ Fb)
{
    extern __shared__ uint32_t sm32[];
    int tid = threadIdx.x, wid = tid >> 5, lane = tid & 31;
    int g = lane >> 2, t4 = lane & 3;
    int m0w = (wid & 3)*32, n0w = (wid >> 2)*32;
    int bh = blockIdx.x, t0 = blockIdx.y << 7;

    uint32_t sb = smem_u32(sm32);
    uint32_t lrow = lane & 15, lsel = (lane >> 4) << 4;
    uint32_t aoffH = sb + (m0w + lrow)*A_STRIDE_B + lsel;
    uint32_t aoffL = aoffH + 18432;
    uint32_t boffH = sb + 36864 + (n0w + lrow)*A_STRIDE_B + lsel;
    uint32_t boffL = boffH + 9216;

    float acc[2][4][4];
#pragma unroll
    for (int mi = 0; mi < 2; mi++)
#pragma unroll
        for (int nj = 0; nj < 4; nj++)
#pragma unroll
            for (int q = 0; q < 4; q++) acc[mi][nj][q] = 0.f;

    const uint4* gA4h = (const uint4*)(g_Fwh + (size_t)t0*NS);
    const uint4* gA4l = (const uint4*)(g_Fwl + (size_t)t0*NS);
    const uint4* gB4h = (const uint4*)(g_Vth + (size_t)bh*NDH*NS);
    const uint4* gB4l = (const uint4*)(g_Vtl + (size_t)bh*NDH*NS);

    for (int ch = 0; ch < 8; ch++) {
        __syncthreads();
        for (int i = tid; i < 1024; i += 256) {
            int r = i >> 3, c = i & 7;
            cp16(sb + (r*36 + c*4)*4,        gA4h + (size_t)r*64 + ch*8 + c);
            cp16(sb + (4608 + r*36 + c*4)*4, gA4l + (size_t)r*64 + ch*8 + c);
        }
        for (int i = tid; i < 512; i += 256) {
            int r = i >> 3, c = i & 7;
            cp16(sb + (9216 + r*36 + c*4)*4,  gB4h + (size_t)r*64 + ch*8 + c);
            cp16(sb + (11520 + r*36 + c*4)*4, gB4l + (size_t)r*64 + ch*8 + c);
        }
        cp_wait();
        __syncthreads();
        MMA_CHUNK_LDSM();
    }

    __syncthreads();
    float* Sg = (float*)sm32;
#pragma unroll
    for (int mi = 0; mi < 2; mi++) {
        int m = m0w + mi*16 + g;
        float f0 = Fb[t0 + m];
        float f1 = Fb[t0 + m + 8];
#pragma unroll
        for (int nj = 0; nj < 4; nj++) {
            int n = n0w + nj*8 + t4*2;
            Sg[n*129 + m]         = acc[mi][nj][0] + f0;
            Sg[(n+1)*129 + m]     = acc[mi][nj][1] + f0;
            Sg[n*129 + m + 8]     = acc[mi][nj][2] + f1;
            Sg[(n+1)*129 + m + 8] = acc[mi][nj][3] + f1;
        }
    }
    __syncthreads();
    size_t base = (size_t)bh*NDH*NT;
    for (int i = tid; i < 4096; i += 256) {
        int d = i >> 6, mm = (i & 63)*2;
        uint32_t hi, lo;
        split2(Sg[d*129 + mm], Sg[d*129 + mm + 1], hi, lo);
        size_t idx = base + (size_t)d*NT + t0 + mm;
        *(uint32_t*)(g_VFth + idx) = hi;
        *(uint32_t*)(g_VFtl + idx) = lo;
    }
}

// ---------------------------------------------------------------------------
// k_attn_fused (occ 2, cp.async staging)
// ---------------------------------------------------------------------------
__global__ void __launch_bounds__(256, 2) k_attn_fused(float* __restrict__ attn_out)
{
    extern __shared__ uint32_t sm32[];
    float* sredm = (float*)(sm32 + 20736);
    float* sreds = (float*)(sm32 + 20992);
    int tid = threadIdx.x, wid = tid >> 5, lane = tid & 31;
    int g = lane >> 2, t4 = lane & 3;
    int s0 = blockIdx.x << 5, bh = blockIdx.y;

    uint32_t sb = smem_u32(sm32);
    uint32_t lrow = lane & 15, lsel = (lane >> 4) << 4;
    uint32_t aoffH = sb + 73728 + lrow*A_STRIDE_B + lsel;
    uint32_t aoffL = aoffH + 4608;
    uint32_t boffH = sb + (wid*32 + lrow)*A_STRIDE_B + lsel;
    uint32_t boffL = boffH + 36864;

    const uint4* gQ4h = (const uint4*)(g_Qh + ((size_t)bh*NS + s0)*NDH);
    const uint4* gQ4l = (const uint4*)(g_Ql + ((size_t)bh*NS + s0)*NDH);
    {
        int r = tid >> 3, c = tid & 7;
        cp16(sb + (18432 + r*36 + c*4)*4, gQ4h + (size_t)r*8 + c);
        cp16(sb + (19584 + r*36 + c*4)*4, gQ4l + (size_t)r*8 + c);
    }

    float acc[2][8][4];
#pragma unroll
    for (int mi = 0; mi < 2; mi++)
#pragma unroll
        for (int nj = 0; nj < 8; nj++)
#pragma unroll
            for (int q = 0; q < 4; q++) acc[mi][nj][q] = 0.f;

    const uint4* gKE4h = (const uint4*)(g_KEh + (size_t)bh*NT*NDH);
    const uint4* gKE4l = (const uint4*)(g_KEl + (size_t)bh*NT*NDH);

    for (int chn = 0; chn < 2; chn++) {
        if (chn) __syncthreads();
        for (int i = tid; i < 2048; i += 256) {
            int r = i >> 3, c = i & 7;
            cp16(sb + (r*36 + c*4)*4,        gKE4h + (size_t)(chn*256 + r)*8 + c);
            cp16(sb + (9216 + r*36 + c*4)*4, gKE4l + (size_t)(chn*256 + r)*8 + c);
        }
        cp_wait();
        __syncthreads();
#pragma unroll
        for (int ks = 0; ks < 4; ks++) {
            uint32_t ah[2][4], al[2][4];
#pragma unroll
            for (int mi = 0; mi < 2; mi++) {
                ldmx4(ah[mi][0],ah[mi][1],ah[mi][2],ah[mi][3], aoffH + mi*MI_STEP_B + ks*KS_STEP_B);
                ldmx4(al[mi][0],al[mi][1],al[mi][2],al[mi][3], aoffL + mi*MI_STEP_B + ks*KS_STEP_B);
            }
#pragma unroll
            for (int nj2 = 0; nj2 < 2; nj2++) {
                uint32_t bhp[4], blp[4];
                ldmx4(bhp[0],bhp[1],bhp[2],bhp[3], boffH + nj2*MI_STEP_B + ks*KS_STEP_B);
                ldmx4(blp[0],blp[1],blp[2],blp[3], boffL + nj2*MI_STEP_B + ks*KS_STEP_B);
#pragma unroll
                for (int jj = 0; jj < 2; jj++) {
                    int nj = chn*4 + nj2*2 + jj;
#pragma unroll
                    for (int mi = 0; mi < 2; mi++) {
                        mma16816(acc[mi][nj], ah[mi][0],ah[mi][1],ah[mi][2],ah[mi][3], bhp[jj], bhp[jj+2]);
                        mma16816(acc[mi][nj], ah[mi][0],ah[mi][1],ah[mi][2],ah[mi][3], blp[jj], blp[jj+2]);
                        mma16816(acc[mi][nj], al[mi][0],al[mi][1],al[mi][2],al[mi][3], bhp[jj], bhp[jj+2]);
                    }
                }
            }
        }
    }

    // ---- softmax ----
    float lm[2][2];
#pragma unroll
    for (int mi = 0; mi < 2; mi++) { lm[mi][0] = -1e30f; lm[mi][1] = -1e30f; }
#pragma unroll
    for (int mi = 0; mi < 2; mi++)
#pragma unroll
        for (int nj = 0; nj < 8; nj++) {
#pragma unroll
            for (int q = 0; q < 4; q++) acc[mi][nj][q] *= 0.125f;
            lm[mi][0] = fmaxf(lm[mi][0], fmaxf(acc[mi][nj][0], acc[mi][nj][1]));
            lm[mi][1] = fmaxf(lm[mi][1], fmaxf(acc[mi][nj][2], acc[mi][nj][3]));
        }
#pragma unroll
    for (int mi = 0; mi < 2; mi++)
#pragma unroll
        for (int hh = 0; hh < 2; hh++) {
            lm[mi][hh] = fmaxf(lm[mi][hh], __shfl_xor_sync(0xffffffffu, lm[mi][hh], 1));
            lm[mi][hh] = fmaxf(lm[mi][hh], __shfl_xor_sync(0xffffffffu, lm[mi][hh], 2));
        }
    if (t4 == 0) {
#pragma unroll
        for (int mi = 0; mi < 2; mi++) {
            sredm[wid*32 + mi*16 + g]     = lm[mi][0];
            sredm[wid*32 + mi*16 + g + 8] = lm[mi][1];
        }
    }
    __syncthreads();
    float rowm[2][2];
#pragma unroll
    for (int mi = 0; mi < 2; mi++)
#pragma unroll
        for (int hh = 0; hh < 2; hh++) {
            int row = mi*16 + g + hh*8;
            float m = sredm[row];
#pragma unroll
            for (int w = 1; w < 8; w++) m = fmaxf(m, sredm[w*32 + row]);
            rowm[mi][hh] = m;
        }
    float ls[2][2] = {{0.f,0.f},{0.f,0.f}};
#pragma unroll
    for (int mi = 0; mi < 2; mi++)
#pragma unroll
        for (int nj = 0; nj < 8; nj++) {
            acc[mi][nj][0] = __expf(acc[mi][nj][0] - rowm[mi][0]);
            acc[mi][nj][1] = __expf(acc[mi][nj][1] - rowm[mi][0]);
            acc[mi][nj][2] = __expf(acc[mi][nj][2] - rowm[mi][1]);
            acc[mi][nj][3] = __expf(acc[mi][nj][3] - rowm[mi][1]);
            ls[mi][0] += acc[mi][nj][0] + acc[mi][nj][1];
            ls[mi][1] += acc[mi][nj][2] + acc[mi][nj][3];
        }
#pragma unroll
    for (int mi = 0; mi < 2; mi++)
#pragma unroll
        for (int hh = 0; hh < 2; hh++) {
            ls[mi][hh] += __shfl_xor_sync(0xffffffffu, ls[mi][hh], 1);
            ls[mi][hh] += __shfl_xor_sync(0xffffffffu, ls[mi][hh], 2);
        }
    if (t4 == 0) {
#pragma unroll
        for (int mi = 0; mi < 2; mi++) {
            sreds[wid*32 + mi*16 + g]     = ls[mi][0];
            sreds[wid*32 + mi*16 + g + 8] = ls[mi][1];
        }
    }
    __syncthreads();
    float inv[2][2];
#pragma unroll
    for (int mi = 0; mi < 2; mi++)
#pragma unroll
        for (int hh = 0; hh < 2; hh++) {
            int row = mi*16 + g + hh*8;
            float s = 0.f;
#pragma unroll
            for (int w = 0; w < 8; w++) s += sreds[w*32 + row];
            inv[mi][hh] = 1.f / s;
        }

    // normalize, write attn, convert P -> bf16 split fragments
    uint32_t pah[4][2][4], pal[4][2][4];
#pragma unroll
    for (int hf = 0; hf < 2; hf++)
#pragma unroll
        for (int ks2 = 0; ks2 < 2; ks2++) {
            int ke = hf*2 + ks2;
#pragma unroll
            for (int mi = 0; mi < 2; mi++) {
                int nj0 = hf*4 + ks2*2, nj1 = nj0 + 1;
                size_t r0 = ((size_t)bh*NS + s0 + mi*16 + g)*NT;
                size_t r1 = r0 + 8*NT;
                int c0 = hf*256 + wid*32 + ks2*16 + 2*t4;
                acc[mi][nj0][0] *= inv[mi][0];  acc[mi][nj0][1] *= inv[mi][0];
                acc[mi][nj0][2] *= inv[mi][1];  acc[mi][nj0][3] *= inv[mi][1];
                acc[mi][nj1][0] *= inv[mi][0];  acc[mi][nj1][1] *= inv[mi][0];
                acc[mi][nj1][2] *= inv[mi][1];  acc[mi][nj1][3] *= inv[mi][1];
                *(float2*)(attn_out + r0 + c0)     = make_float2(acc[mi][nj0][0], acc[mi][nj0][1]);
                *(float2*)(attn_out + r1 + c0)     = make_float2(acc[mi][nj0][2], acc[mi][nj0][3]);
                *(float2*)(attn_out + r0 + c0 + 8) = make_float2(acc[mi][nj1][0], acc[mi][nj1][1]);
                *(float2*)(attn_out + r1 + c0 + 8) = make_float2(acc[mi][nj1][2], acc[mi][nj1][3]);
                split2(acc[mi][nj0][0], acc[mi][nj0][1], pah[ke][mi][0], pal[ke][mi][0]);
                split2(acc[mi][nj0][2], acc[mi][nj0][3], pah[ke][mi][1], pal[ke][mi][1]);
                split2(acc[mi][nj1][0], acc[mi][nj1][1], pah[ke][mi][2], pal[ke][mi][2]);
                split2(acc[mi][nj1][2], acc[mi][nj1][3], pah[ke][mi][3], pal[ke][mi][3]);
            }
        }

    // ---- P·VF in two d-halves ----
    const uint4* gVF4h = (const uint4*)(g_VFth + (size_t)bh*NDH*NT);
    const uint4* gVF4l = (const uint4*)(g_VFtl + (size_t)bh*NDH*NT);
    uint32_t b_pvH = sb + lrow*528 + wid*64 + lsel;
    uint32_t b_pvL = b_pvH + 16896;

    for (int dh = 0; dh < 2; dh++) {
        float acc_o[2][4][4];
#pragma unroll
        for (int mi = 0; mi < 2; mi++)
#pragma unroll
            for (int nd = 0; nd < 4; nd++)
#pragma unroll
                for (int q = 0; q < 4; q++) acc_o[mi][nd][q] = 0.f;

        for (int hf = 0; hf < 2; hf++) {
            __syncthreads();
            for (int i = tid; i < 1024; i += 256) {
                int r = i >> 5, c = i & 31;
                cp16(sb + (r*132 + c*4)*4,        gVF4h + (size_t)(dh*32 + r)*64 + hf*32 + c);
                cp16(sb + (4224 + r*132 + c*4)*4, gVF4l + (size_t)(dh*32 + r)*64 + hf*32 + c);
            }
            cp_wait();
            __syncthreads();
#pragma unroll
            for (int dt = 0; dt < 2; dt++) {
#pragma unroll
                for (int ks2 = 0; ks2 < 2; ks2++) {
                    int ke = hf*2 + ks2;
                    uint32_t bhv[4], blv[4];
                    ldmx4(bhv[0],bhv[1],bhv[2],bhv[3], b_pvH + dt*8448 + ks2*32);
                    ldmx4(blv[0],blv[1],blv[2],blv[3], b_pvL + dt*8448 + ks2*32);
#pragma unroll
                    for (int jj = 0; jj < 2; jj++) {
                        int nd = dt*2 + jj;
#pragma unroll
                        for (int mi = 0; mi < 2; mi++) {
                            mma16816(acc_o[mi][nd], pah[ke][mi][0],pah[ke][mi][1],pah[ke][mi][2],pah[ke][mi][3], bhv[jj], bhv[jj+2]);
                            mma16816(acc_o[mi][nd], pah[ke][mi][0],pah[ke][mi][1],pah[ke][mi][2],pah[ke][mi][3], blv[jj], blv[jj+2]);
                            mma16816(acc_o[mi][nd], pal[ke][mi][0],pal[ke][mi][1],pal[ke][mi][2],pal[ke][mi][3], bhv[jj], bhv[jj+2]);
                        }
                    }
                }
            }
        }

        __syncthreads();
        float* Ob = (float*)sm32;
#pragma unroll
        for (int mi = 0; mi < 2; mi++)
#pragma unroll
            for (int nd = 0; nd < 4; nd++) {
                int m = mi*16 + g, n = nd*8 + 2*t4;
                Ob[wid*1056 + m*33 + n]       = acc_o[mi][nd][0];
                Ob[wid*1056 + m*33 + n + 1]   = acc_o[mi][nd][1];
                Ob[wid*1056 + (m+8)*33 + n]   = acc_o[mi][nd][2];
                Ob[wid*1056 + (m+8)*33 + n+1] = acc_o[mi][nd][3];
            }
        __syncthreads();
        {
            int s = tid >> 3, dg = (tid & 7)*4;
            float o[4] = {0.f, 0.f, 0.f, 0.f};
#pragma unroll
            for (int w = 0; w < 8; w++)
#pragma unroll
                for (int j = 0; j < 4; j++) o[j] += Ob[w*1056 + s*33 + dg + j];
            size_t base = ((size_t)bh*NS + s0 + s)*NDH + dh*32 + dg;
            uint32_t hi, lo;
            split2(o[0], o[1], hi, lo);
            *(uint32_t*)(g_HOh + base) = hi;     *(uint32_t*)(g_HOl + base) = lo;
            split2(o[2], o[3], hi, lo);
            *(uint32_t*)(g_HOh + base + 2) = hi; *(uint32_t*)(g_HOl + base + 2) = lo;
        }
    }
}

// ---------------------------------------------------------------------------
// k_out_mma
// ---------------------------------------------------------------------------
__global__ void __launch_bounds__(256, 3) k_out_mma(const float* __restrict__ Ob,
                                                    float* __restrict__ out)
{
    extern __shared__ uint32_t sm32[];
    int tid = threadIdx.x, wid = tid >> 5, lane = tid & 31;
    int g = lane >> 2, t4 = lane & 3;
    int m0w = (wid & 3)*32, n0w = (wid >> 2)*32;
    int m0 = blockIdx.x << 7;
    int b  = blockIdx.x >> 2;
    int sbase = (blockIdx.x & 3) << 7;
    int n0 = blockIdx.y << 6;

    uint32_t sb = smem_u32(sm32);
    uint32_t lrow = lane & 15, lsel = (lane >> 4) << 4;
    uint32_t aoffH = sb + (m0w + lrow)*A_STRIDE_B + lsel;
    uint32_t aoffL = aoffH + 18432;
    uint32_t boffH = sb + 36864 + (n0w + lrow)*A_STRIDE_B + lsel;
    uint32_t boffL = boffH + 9216;

    float acc[2][4][4];
#pragma unroll
    for (int mi = 0; mi < 2; mi++)
#pragma unroll
        for (int nj = 0; nj < 4; nj++)
#pragma unroll
            for (int q = 0; q < 4; q++) acc[mi][nj][q] = 0.f;

    for (int kc = 0; kc < 16; kc++) {
        const uint4* gA4h = (const uint4*)(g_HOh + ((size_t)(b*NH + kc)*NS + sbase)*NDH);
        const uint4* gA4l = (const uint4*)(g_HOl + ((size_t)(b*NH + kc)*NS + sbase)*NDH);
        const uint4* gB4h = (const uint4*)(g_Owh + (size_t)n0*NDM);
        const uint4* gB4l = (const uint4*)(g_Owl + (size_t)n0*NDM);
        __syncthreads();
        for (int i = tid; i < 1024; i += 256) {
            int r = i >> 3, c = i & 7;
            cp16(sb + (r*36 + c*4)*4,        gA4h + (size_t)r*8 + c);
            cp16(sb + (4608 + r*36 + c*4)*4, gA4l + (size_t)r*8 + c);
        }
        for (int i = tid; i < 512; i += 256) {
            int r = i >> 3, c = i & 7;
            cp16(sb + (9216 + r*36 + c*4)*4,  gB4h + (size_t)r*128 + kc*8 + c);
            cp16(sb + (11520 + r*36 + c*4)*4, gB4l + (size_t)r*128 + kc*8 + c);
        }
        cp_wait();
        __syncthreads();
        MMA_CHUNK_LDSM();
    }

    __syncthreads();
    float* Sg = (float*)sm32;
#pragma unroll
    for (int mi = 0; mi < 2; mi++) {
        int m = m0w + mi*16 + g;
#pragma unroll
        for (int nj = 0; nj < 4; nj++) {
            int n = n0w + nj*8 + t4*2;
            float o0 = Ob[n0 + n];
            float o1 = Ob[n0 + n + 1];
            Sg[m*65 + n]         = acc[mi][nj][0] + o0;
            Sg[m*65 + n + 1]     = acc[mi][nj][1] + o1;
            Sg[(m+8)*65 + n]     = acc[mi][nj][2] + o0;
            Sg[(m+8)*65 + n + 1] = acc[mi][nj][3] + o1;
        }
    }
    __syncthreads();
    for (int i = tid; i < 8192; i += 256) {
        int r = i >> 6, c = i & 63;
        out[(size_t)(m0 + r)*NDM + n0 + c] = Sg[r*65 + c];
    }
}

// ---------------------------------------------------------------------------
extern "C" void kernel_launch(void* const* d_in, const int* in_sizes, int n_in,
                              void* d_out, int out_size)
{
    const float* query = (const float*)d_in[0];
    const float* key   = (const float*)d_in[1];
    const float* value = (const float*)d_in[2];
    const float* Wq    = (const float*)d_in[3];
    const float* bq    = (const float*)d_in[4];
    const float* Wk    = (const float*)d_in[5];
    const float* bk    = (const float*)d_in[6];
    const float* Wv    = (const float*)d_in[7];
    const float* bv    = (const float*)d_in[8];
    const float* E_w   = (const float*)d_in[9];
    const float* E_b   = (const float*)d_in[10];
    const float* F_w   = (const float*)d_in[11];
    const float* F_b   = (const float*)d_in[12];
    const float* out_w = (const float*)d_in[13];
    const float* out_b = (const float*)d_in[14];

    const long long mha_elems  = (long long)NB*NS*NDM;
    const long long attn_elems = (long long)BH*NS*NT;

    float* outp = (float*)d_out;
    float* mha_ptr;
    float* attn_ptr;
    if ((long long)out_size >= mha_elems + attn_elems) {
        mha_ptr  = outp;
        attn_ptr = outp + mha_elems;
    } else if ((long long)out_size == attn_elems) {
        attn_ptr = outp;
        cudaGetSymbolAddress((void**)&mha_ptr, g_MHA_FB);
    } else {
        mha_ptr = outp;
        cudaGetSymbolAddress((void**)&attn_ptr, g_ATTN_FB);
    }

    cudaFuncSetAttribute(k_qkv_mma,    cudaFuncAttributeMaxDynamicSharedMemorySize, 55296);
    cudaFuncSetAttribute(k_ke_mma,     cudaFuncAttributeMaxDynamicSharedMemorySize, 55296);
    cudaFuncSetAttribute(k_vf_mma,     cudaFuncAttributeMaxDynamicSharedMemorySize, 55296);
    cudaFuncSetAttribute(k_out_mma,    cudaFuncAttributeMaxDynamicSharedMemorySize, 55296);
    cudaFuncSetAttribute(k_attn_fused, cudaFuncAttributeMaxDynamicSharedMemorySize, 84992);

    k_split6<<<(3*NX + 3*NW + 255)/256, 256>>>(query, key, value, Wq, Wk, Wv);
    k_split3<<<(2*NT*NS + NDM*NDM + 255)/256, 256>>>(E_w, F_w, out_w);
    k_qkv_mma<<<dim3(BH, 4, 3), 256, 55296>>>(bq, bk, bv);
    k_ke_mma<<<dim3(BH, 4), 256, 55296>>>(E_b);
    k_vf_mma<<<dim3(BH, 4), 256, 55296>>>(F_b);
    k_attn_fused<<<dim3(16, BH), 256, 84992>>>(attn_ptr);
    k_out_mma<<<dim3((NB*NS)/128, NDM/64), 256, 55296>>>(out_b, mha_ptr);
}